// round 3
// baseline (speedup 1.0000x reference)
#include <cuda_runtime.h>
#include <math.h>
#include <stdint.h>

#define BB   8
#define QQ   1024
#define EE   256
#define NHH  8
#define DHH  32
#define LLV  4
#define PPV  4
#define STOT 21760

// ---------------- scratch (device globals: allocation-free) ----------------
__device__ float g_qk   [BB*QQ*EE];
__device__ float g_qk2  [BB*QQ*512];          // merged q|k projections
__device__ float g_v    [BB*QQ*EE];
__device__ float g_ctx  [BB*QQ*EE];
__device__ float g_tmp  [BB*QQ*EE];
__device__ float g_tgt1 [BB*QQ*EE];
__device__ float g_query[BB*QQ*EE];
__device__ float g_value[(size_t)BB*STOT*EE];
__device__ float g_off  [BB*QQ*EE];
__device__ float g_aw   [BB*QQ*128];
__device__ float g_samp [BB*QQ*EE];
__device__ float g_tgt2 [BB*QQ*EE];
__device__ float g_ffn1 [BB*QQ*4*EE];

// ---------------- elementwise add (vectorized) ----------------
__global__ void add_kernel(const float4* __restrict__ a, const float4* __restrict__ b,
                           float4* __restrict__ c, int n4) {
    int i = blockIdx.x * blockDim.x + threadIdx.x;
    if (i < n4) {
        float4 x = a[i], y = b[i];
        c[i] = make_float4(x.x + y.x, x.y + y.y, x.z + y.z, x.w + y.w);
    }
}

// ---------------- mma helper ----------------
__device__ __forceinline__ void mma_tf32(float* c,
                                         uint32_t a0, uint32_t a1, uint32_t a2, uint32_t a3,
                                         uint32_t b0, uint32_t b1) {
    asm volatile("mma.sync.aligned.m16n8k8.row.col.f32.tf32.tf32.f32 "
                 "{%0,%1,%2,%3}, {%4,%5,%6,%7}, {%8,%9}, {%0,%1,%2,%3};\n"
                 : "+f"(c[0]), "+f"(c[1]), "+f"(c[2]), "+f"(c[3])
                 : "r"(a0), "r"(a1), "r"(a2), "r"(a3), "r"(b0), "r"(b1));
}

__device__ __forceinline__ void cp_async16(uint32_t smem_addr, const void* gmem) {
    asm volatile("cp.async.ca.shared.global [%0], [%1], 16;\n" :: "r"(smem_addr), "l"(gmem));
}

// ---------------- tensor-core GEMM (double-buffered cp.async) --------------
// C[M,N] = A[M,K] @ W[N,K]^T + bias.  128x128 tile, 256 thr (8 warps 4m x 2n).
// Raw fp32 bits fed to tf32 mma (HW truncates mantissa).
#define SMS 36                       // smem row stride (conflict-free)
#define STAGE_U32 (128 * SMS)        // one matrix, one stage
template<int RELU>
__global__ __launch_bounds__(256, 1)
void gemm_tc(const float* __restrict__ A, const float* __restrict__ W,
             const float* __restrict__ bias, float* __restrict__ C,
             int M, int N, int K) {
    extern __shared__ uint32_t sm[];
    // layout: A stage0, A stage1, W stage0, W stage1
    uint32_t* Abuf[2] = { sm,                sm + STAGE_U32 };
    uint32_t* Wbuf[2] = { sm + 2*STAGE_U32,  sm + 3*STAGE_U32 };

    const int bm = blockIdx.y * 128;
    const int bn = blockIdx.x * 128;
    const int tid  = threadIdx.x;
    const int warp = tid >> 5;
    const int lane = tid & 31;
    const int wm = warp >> 1;
    const int wn = warp & 1;
    const int lr = lane >> 2;
    const int lc = lane & 3;

    float acc[2][8][4];
#pragma unroll
    for (int mi = 0; mi < 2; mi++)
#pragma unroll
        for (int ni = 0; ni < 8; ni++)
#pragma unroll
            for (int t = 0; t < 4; t++) acc[mi][ni][t] = 0.f;

    const int lrow  = tid >> 1;          // 0..127
    const int lhalf = (tid & 1) * 16;    // 0 or 16
    const float* Ag = A + (size_t)(bm + lrow) * K + lhalf;
    const float* Wg = W + (size_t)(bn + lrow) * K + lhalf;
    const uint32_t a_dst_base = (uint32_t)__cvta_generic_to_shared((void*)0) ;

    // per-thread smem destinations (byte addresses)
    uint32_t aAddr[2], wAddr[2];
#pragma unroll
    for (int s = 0; s < 2; s++) {
        aAddr[s] = (uint32_t)__cvta_generic_to_shared(&Abuf[s][lrow * SMS + lhalf]);
        wAddr[s] = (uint32_t)__cvta_generic_to_shared(&Wbuf[s][lrow * SMS + lhalf]);
    }

    const int nch = K >> 5;   // K/32

    // prologue: stage 0 = chunk 0
#pragma unroll
    for (int j = 0; j < 4; j++) {
        cp_async16(aAddr[0] + j * 16, Ag + j * 4);
        cp_async16(wAddr[0] + j * 16, Wg + j * 4);
    }
    asm volatile("cp.async.commit_group;\n");

    for (int c = 0; c < nch; c++) {
        const int cur = c & 1;
        if (c + 1 < nch) {
            const float* Agn = Ag + (size_t)(c + 1) * 32;
            const float* Wgn = Wg + (size_t)(c + 1) * 32;
            const int nxt = cur ^ 1;
#pragma unroll
            for (int j = 0; j < 4; j++) {
                cp_async16(aAddr[nxt] + j * 16, Agn + j * 4);
                cp_async16(wAddr[nxt] + j * 16, Wgn + j * 4);
            }
            asm volatile("cp.async.commit_group;\n");
            asm volatile("cp.async.wait_group 1;\n");
        } else {
            asm volatile("cp.async.wait_group 0;\n");
        }
        __syncthreads();

        const uint32_t* As = Abuf[cur];
        const uint32_t* Ws = Wbuf[cur];
#pragma unroll
        for (int kk = 0; kk < 32; kk += 8) {
            uint32_t af[2][4];
#pragma unroll
            for (int mi = 0; mi < 2; mi++) {
                int r0 = (wm * 32 + mi * 16 + lr) * SMS + kk + lc;
                int r1 = r0 + 8 * SMS;
                af[mi][0] = As[r0];
                af[mi][1] = As[r1];
                af[mi][2] = As[r0 + 4];
                af[mi][3] = As[r1 + 4];
            }
#pragma unroll
            for (int ni = 0; ni < 8; ni++) {
                int nb = (wn * 64 + ni * 8 + lr) * SMS + kk + lc;
                uint32_t b0 = Ws[nb];
                uint32_t b1 = Ws[nb + 4];
                mma_tf32(acc[0][ni], af[0][0], af[0][1], af[0][2], af[0][3], b0, b1);
                mma_tf32(acc[1][ni], af[1][0], af[1][1], af[1][2], af[1][3], b0, b1);
            }
        }
        __syncthreads();
    }

    // epilogue
#pragma unroll
    for (int ni = 0; ni < 8; ni++) {
        int col = bn + wn * 64 + ni * 8 + lc * 2;
        float bj0 = bias[col], bj1 = bias[col + 1];
#pragma unroll
        for (int mi = 0; mi < 2; mi++) {
            int row = bm + wm * 32 + mi * 16 + lr;
            float v0 = acc[mi][ni][0] + bj0;
            float v1 = acc[mi][ni][1] + bj1;
            float v2 = acc[mi][ni][2] + bj0;
            float v3 = acc[mi][ni][3] + bj1;
            if (RELU) {
                v0 = fmaxf(v0, 0.f); v1 = fmaxf(v1, 0.f);
                v2 = fmaxf(v2, 0.f); v3 = fmaxf(v3, 0.f);
            }
            *(float2*)(C + (size_t)row * N + col)       = make_float2(v0, v1);
            *(float2*)(C + (size_t)(row + 8) * N + col) = make_float2(v2, v3);
        }
    }
}
#define GEMM_SMEM (4 * STAGE_U32 * 4)   // bytes

// ---------------- self-attention (no-max softmax: scores bounded) ----------
// Q/K from merged buffer (ld 512), V separate (ld 256).
__global__ void attn_kernel(const float* __restrict__ Qm, int ldq,
                            const float* __restrict__ Km, int ldk,
                            const float* __restrict__ Vm, int ldv,
                            float* __restrict__ Om) {
    const int bh = blockIdx.y;
    const int b = bh / NHH, h = bh % NHH;
    const int q = blockIdx.x * 128 + threadIdx.x;
    const float scale = 0.17677669529663687f;

    __shared__ float Ks[64][32];
    __shared__ float Vs[64][32];

    float qreg[32];
    const float* qp = Qm + (size_t)(b * QQ + q) * ldq + h * DHH;
#pragma unroll
    for (int d = 0; d < 32; d++) qreg[d] = qp[d] * scale;

    float lsum = 0.f;
    float acc[32];
#pragma unroll
    for (int d = 0; d < 32; d++) acc[d] = 0.f;

    for (int k0 = 0; k0 < QQ; k0 += 64) {
        int t = threadIdx.x;
#pragma unroll
        for (int r = 0; r < 16; r++) {
            int idx = t + r * 128;
            int kk = idx >> 5, d = idx & 31;
            Ks[kk][d] = Km[(size_t)(b * QQ + k0 + kk) * ldk + h * DHH + d];
            Vs[kk][d] = Vm[(size_t)(b * QQ + k0 + kk) * ldv + h * DHH + d];
        }
        __syncthreads();
#pragma unroll 4
        for (int kk = 0; kk < 64; kk++) {
            float s = 0.f;
#pragma unroll
            for (int d = 0; d < 32; d++) s = fmaf(qreg[d], Ks[kk][d], s);
            float p = __expf(s);
            lsum += p;
#pragma unroll
            for (int d = 0; d < 32; d++) acc[d] = fmaf(p, Vs[kk][d], acc[d]);
        }
        __syncthreads();
    }
    float inv = 1.f / lsum;
    float* op = Om + (size_t)(b * QQ + q) * EE + h * DHH;
#pragma unroll
    for (int d = 0; d < 32; d++) op[d] = acc[d] * inv;
}

// ---------------- residual add + LayerNorm (rows of 256) ----------------
__global__ void addln_kernel(const float* __restrict__ X, const float* __restrict__ Y,
                             const float* __restrict__ gam, const float* __restrict__ bet,
                             float* __restrict__ out) {
    int row = blockIdx.x;
    int t = threadIdx.x;
    size_t base = (size_t)row * EE;
    float x = X[base + t] + Y[base + t];

    __shared__ float red[8];
    __shared__ float mu_s, rstd_s;

    float s = x;
#pragma unroll
    for (int o = 16; o > 0; o >>= 1) s += __shfl_down_sync(0xffffffff, s, o);
    if ((t & 31) == 0) red[t >> 5] = s;
    __syncthreads();
    if (t == 0) {
        float tot = 0.f;
#pragma unroll
        for (int i = 0; i < 8; i++) tot += red[i];
        mu_s = tot * (1.f / EE);
    }
    __syncthreads();
    float mu = mu_s;
    float d = x - mu;
    float s2 = d * d;
#pragma unroll
    for (int o = 16; o > 0; o >>= 1) s2 += __shfl_down_sync(0xffffffff, s2, o);
    if ((t & 31) == 0) red[t >> 5] = s2;
    __syncthreads();
    if (t == 0) {
        float tot = 0.f;
#pragma unroll
        for (int i = 0; i < 8; i++) tot += red[i];
        rstd_s = rsqrtf(tot * (1.f / EE) + 1e-5f);
    }
    __syncthreads();
    out[base + t] = (x - mu) * rstd_s * gam[t] + bet[t];
}

// ---------------- attention-weight softmax over L*P=16 ----------------
__global__ void awsm_kernel(float* __restrict__ aw) {
    int i = blockIdx.x * blockDim.x + threadIdx.x;
    if (i >= BB * QQ * NHH) return;
    float* p = aw + (size_t)i * 16;
    float v[16];
    float m = -1e30f;
#pragma unroll
    for (int j = 0; j < 16; j++) { v[j] = p[j]; m = fmaxf(m, v[j]); }
    float s = 0.f;
#pragma unroll
    for (int j = 0; j < 16; j++) { v[j] = __expf(v[j] - m); s += v[j]; }
    float inv = 1.f / s;
#pragma unroll
    for (int j = 0; j < 16; j++) p[j] = v[j] * inv;
}

// ---------------- deformable bilinear sampling ----------------
__device__ __forceinline__ float fetch_corner(const float* __restrict__ vb,
                                              float yi, float xi, int Hl, int Wl) {
    bool valid = (xi >= 0.f) && (xi <= (float)(Wl - 1)) &&
                 (yi >= 0.f) && (yi <= (float)(Hl - 1));
    int xc = (int)fminf(fmaxf(xi, 0.f), (float)(Wl - 1));
    int yc = (int)fminf(fmaxf(yi, 0.f), (float)(Hl - 1));
    float v = vb[(size_t)(yc * Wl + xc) * EE];
    return valid ? v : 0.f;
}

__global__ void sample_kernel(const float* __restrict__ refp, const float* __restrict__ off,
                              const float* __restrict__ aw, const float* __restrict__ val,
                              float* __restrict__ out) {
    int wg = (blockIdx.x * blockDim.x + threadIdx.x) >> 5;
    int lane = threadIdx.x & 31;
    if (wg >= BB * QQ * NHH) return;
    int h = wg % NHH;
    int bq = wg / NHH;
    int b = bq / QQ;

    const float* rp = refp + (size_t)bq * (LLV * 2);
    const float* op = off + (size_t)bq * 256 + h * 32;
    const float* ap = aw + (size_t)bq * 128 + h * 16;

    const int Hs[4] = {128, 64, 32, 16};
    const int Ws2[4] = {128, 64, 32, 16};
    const int S0[4] = {0, 16384, 20480, 21504};

    float acc = 0.f;
#pragma unroll
    for (int l = 0; l < 4; l++) {
        int Hi = Hs[l], Wi = Ws2[l];
        float Hl = (float)Hi, Wl = (float)Wi;
        const float* vb = val + ((size_t)b * STOT + S0[l]) * EE + h * 32 + lane;
        float rx = rp[l * 2 + 0], ry = rp[l * 2 + 1];
#pragma unroll
        for (int p = 0; p < 4; p++) {
            float ox = op[l * 8 + p * 2 + 0];
            float oy = op[l * 8 + p * 2 + 1];
            float a = ap[l * 4 + p];
            float x = fmaf(rx, Wl, ox) - 0.5f;
            float y = fmaf(ry, Hl, oy) - 0.5f;
            float x0 = floorf(x), y0 = floorf(y);
            float wx = x - x0, wy = y - y0;
            float sum = 0.f;
            sum += fetch_corner(vb, y0,       x0,       Hi, Wi) * (1.f - wy) * (1.f - wx);
            sum += fetch_corner(vb, y0,       x0 + 1.f, Hi, Wi) * (1.f - wy) * wx;
            sum += fetch_corner(vb, y0 + 1.f, x0,       Hi, Wi) * wy * (1.f - wx);
            sum += fetch_corner(vb, y0 + 1.f, x0 + 1.f, Hi, Wi) * wy * wx;
            acc = fmaf(a, sum, acc);
        }
    }
    out[(size_t)bq * EE + h * 32 + lane] = acc;
}

// ---------------- launch ----------------
extern "C" void kernel_launch(void* const* d_in, const int* in_sizes, int n_in,
                              void* d_out, int out_size) {
    const float* tgt   = (const float*)d_in[0];
    const float* qpos  = (const float*)d_in[1];
    const float* refp  = (const float*)d_in[2];
    const float* src   = (const float*)d_in[3];
    const float* ipw   = (const float*)d_in[6];
    const float* ipb   = (const float*)d_in[7];
    const float* outpw = (const float*)d_in[8];
    const float* outpb = (const float*)d_in[9];
    const float* n1g   = (const float*)d_in[10];
    const float* n1b   = (const float*)d_in[11];
    const float* offw  = (const float*)d_in[12];
    const float* offb  = (const float*)d_in[13];
    const float* aww   = (const float*)d_in[14];
    const float* awb   = (const float*)d_in[15];
    const float* vpw   = (const float*)d_in[16];
    const float* vpb   = (const float*)d_in[17];
    const float* opw   = (const float*)d_in[18];
    const float* opb   = (const float*)d_in[19];
    const float* n2g   = (const float*)d_in[20];
    const float* n2b   = (const float*)d_in[21];
    const float* w1    = (const float*)d_in[22];
    const float* b1    = (const float*)d_in[23];
    const float* w2    = (const float*)d_in[24];
    const float* b2    = (const float*)d_in[25];
    const float* n3g   = (const float*)d_in[26];
    const float* n3b   = (const float*)d_in[27];
    float* out = (float*)d_out;

    float *qk, *qk2, *v, *ctx, *tmp, *tgt1, *query, *value, *off, *aw, *samp, *tgt2, *ffn1;
    cudaGetSymbolAddress((void**)&qk,    g_qk);
    cudaGetSymbolAddress((void**)&qk2,   g_qk2);
    cudaGetSymbolAddress((void**)&v,     g_v);
    cudaGetSymbolAddress((void**)&ctx,   g_ctx);
    cudaGetSymbolAddress((void**)&tmp,   g_tmp);
    cudaGetSymbolAddress((void**)&tgt1,  g_tgt1);
    cudaGetSymbolAddress((void**)&query, g_query);
    cudaGetSymbolAddress((void**)&value, g_value);
    cudaGetSymbolAddress((void**)&off,   g_off);
    cudaGetSymbolAddress((void**)&aw,    g_aw);
    cudaGetSymbolAddress((void**)&samp,  g_samp);
    cudaGetSymbolAddress((void**)&tgt2,  g_tgt2);
    cudaGetSymbolAddress((void**)&ffn1,  g_ffn1);

    static bool attr_set = false;
    if (!attr_set) {
        cudaFuncSetAttribute(gemm_tc<0>, cudaFuncAttributeMaxDynamicSharedMemorySize, GEMM_SMEM);
        cudaFuncSetAttribute(gemm_tc<1>, cudaFuncAttributeMaxDynamicSharedMemorySize, GEMM_SMEM);
        attr_set = true;
    }

    const int M = BB * QQ;          // 8192
    const int n_el = M * EE;

    // 1) qk = tgt + query_pos
    add_kernel<<<(n_el / 4 + 255) / 256, 256>>>((const float4*)tgt, (const float4*)qpos,
                                                (float4*)qk, n_el / 4);

    // 2) merged q|k projection (N=512) + v projection
    gemm_tc<0><<<dim3(4, M / 128), 256, GEMM_SMEM>>>(qk,  ipw,             ipb,       qk2, M, 512, 256);
    gemm_tc<0><<<dim3(2, M / 128), 256, GEMM_SMEM>>>(tgt, ipw + 512 * 256, ipb + 512, v,   M, 256, 256);

    // 3) self-attention
    attn_kernel<<<dim3(QQ / 128, BB * NHH), 128>>>(qk2, 512, qk2 + 256, 512, v, 256, ctx);

    // 4) out projection + LN1
    gemm_tc<0><<<dim3(2, M / 128), 256, GEMM_SMEM>>>(ctx, outpw, outpb, tmp, M, 256, 256);
    addln_kernel<<<M, 256>>>(tgt, tmp, n1g, n1b, tgt1);

    // 5) query = tgt1 + query_pos
    add_kernel<<<(n_el / 4 + 255) / 256, 256>>>((const float4*)tgt1, (const float4*)qpos,
                                                (float4*)query, n_el / 4);

    // 6) value projection (174080 x 256 x 256)
    gemm_tc<0><<<dim3(2, (BB * STOT) / 128), 256, GEMM_SMEM>>>(src, vpw, vpb, value, BB * STOT, 256, 256);

    // 7) offsets + attention weights
    gemm_tc<0><<<dim3(2, M / 128), 256, GEMM_SMEM>>>(query, offw, offb, off, M, 256, 256);
    gemm_tc<0><<<dim3(1, M / 128), 256, GEMM_SMEM>>>(query, aww, awb, aw, M, 128, 256);
    awsm_kernel<<<(BB * QQ * NHH + 255) / 256, 256>>>(aw);

    // 8) deformable sampling
    sample_kernel<<<(BB * QQ * NHH) / 8, 256>>>(refp, off, aw, value, samp);

    // 9) output projection + LN2
    gemm_tc<0><<<dim3(2, M / 128), 256, GEMM_SMEM>>>(samp, opw, opb, tmp, M, 256, 256);
    addln_kernel<<<M, 256>>>(tgt1, tmp, n2g, n2b, tgt2);

    // 10) FFN + LN3
    gemm_tc<1><<<dim3(8, M / 128), 256, GEMM_SMEM>>>(tgt2, w1, b1, ffn1, M, 1024, 256);
    gemm_tc<0><<<dim3(2, M / 128), 256, GEMM_SMEM>>>(ffn1, w2, b2, tmp, M, 256, 1024);
    addln_kernel<<<M, 256>>>(tgt2, tmp, n3g, n3b, out);
}

// round 4
// speedup vs baseline: 1.2186x; 1.2186x over previous
#include <cuda_runtime.h>
#include <math.h>
#include <stdint.h>

#define BB   8
#define QQ   1024
#define EE   256
#define NHH  8
#define DHH  32
#define LLV  4
#define PPV  4
#define STOT 21760

// ---------------- scratch (device globals: allocation-free) ----------------
__device__ float g_qk   [BB*QQ*EE];
__device__ float g_qk2  [BB*QQ*512];          // merged q|k projections
__device__ float g_v    [BB*QQ*EE];
__device__ float g_ctx  [BB*QQ*EE];
__device__ float g_tmp  [BB*QQ*EE];
__device__ float g_tgt1 [BB*QQ*EE];
__device__ float g_query[BB*QQ*EE];
__device__ float g_value[(size_t)BB*STOT*EE];
__device__ float g_off  [BB*QQ*EE];
__device__ float g_aw   [BB*QQ*128];
__device__ float g_samp [BB*QQ*EE];
__device__ float g_tgt2 [BB*QQ*EE];
__device__ float g_ffn1 [BB*QQ*4*EE];

// ---------------- elementwise add (vectorized) ----------------
__global__ void add_kernel(const float4* __restrict__ a, const float4* __restrict__ b,
                           float4* __restrict__ c, int n4) {
    int i = blockIdx.x * blockDim.x + threadIdx.x;
    if (i < n4) {
        float4 x = a[i], y = b[i];
        c[i] = make_float4(x.x + y.x, x.y + y.y, x.z + y.z, x.w + y.w);
    }
}

// ---------------- mma helper ----------------
__device__ __forceinline__ void mma_tf32(float* c,
                                         uint32_t a0, uint32_t a1, uint32_t a2, uint32_t a3,
                                         uint32_t b0, uint32_t b1) {
    asm volatile("mma.sync.aligned.m16n8k8.row.col.f32.tf32.tf32.f32 "
                 "{%0,%1,%2,%3}, {%4,%5,%6,%7}, {%8,%9}, {%0,%1,%2,%3};\n"
                 : "+f"(c[0]), "+f"(c[1]), "+f"(c[2]), "+f"(c[3])
                 : "r"(a0), "r"(a1), "r"(a2), "r"(a3), "r"(b0), "r"(b1));
}

__device__ __forceinline__ void cp_async16(uint32_t smem_addr, const void* gmem) {
    asm volatile("cp.async.ca.shared.global [%0], [%1], 16;\n" :: "r"(smem_addr), "l"(gmem));
}

// ---------------- tensor-core GEMM (double-buffered cp.async) --------------
#define SMS 36
#define STAGE_U32 (128 * SMS)
template<int RELU>
__global__ __launch_bounds__(256, 1)
void gemm_tc(const float* __restrict__ A, const float* __restrict__ W,
             const float* __restrict__ bias, float* __restrict__ C,
             int M, int N, int K) {
    extern __shared__ uint32_t sm[];
    uint32_t* Abuf[2] = { sm,                sm + STAGE_U32 };
    uint32_t* Wbuf[2] = { sm + 2*STAGE_U32,  sm + 3*STAGE_U32 };

    const int bm = blockIdx.y * 128;
    const int bn = blockIdx.x * 128;
    const int tid  = threadIdx.x;
    const int warp = tid >> 5;
    const int lane = tid & 31;
    const int wm = warp >> 1;
    const int wn = warp & 1;
    const int lr = lane >> 2;
    const int lc = lane & 3;

    float acc[2][8][4];
#pragma unroll
    for (int mi = 0; mi < 2; mi++)
#pragma unroll
        for (int ni = 0; ni < 8; ni++)
#pragma unroll
            for (int t = 0; t < 4; t++) acc[mi][ni][t] = 0.f;

    const int lrow  = tid >> 1;
    const int lhalf = (tid & 1) * 16;
    const float* Ag = A + (size_t)(bm + lrow) * K + lhalf;
    const float* Wg = W + (size_t)(bn + lrow) * K + lhalf;

    uint32_t aAddr[2], wAddr[2];
#pragma unroll
    for (int s = 0; s < 2; s++) {
        aAddr[s] = (uint32_t)__cvta_generic_to_shared(&Abuf[s][lrow * SMS + lhalf]);
        wAddr[s] = (uint32_t)__cvta_generic_to_shared(&Wbuf[s][lrow * SMS + lhalf]);
    }

    const int nch = K >> 5;

#pragma unroll
    for (int j = 0; j < 4; j++) {
        cp_async16(aAddr[0] + j * 16, Ag + j * 4);
        cp_async16(wAddr[0] + j * 16, Wg + j * 4);
    }
    asm volatile("cp.async.commit_group;\n");

    for (int c = 0; c < nch; c++) {
        const int cur = c & 1;
        if (c + 1 < nch) {
            const float* Agn = Ag + (size_t)(c + 1) * 32;
            const float* Wgn = Wg + (size_t)(c + 1) * 32;
            const int nxt = cur ^ 1;
#pragma unroll
            for (int j = 0; j < 4; j++) {
                cp_async16(aAddr[nxt] + j * 16, Agn + j * 4);
                cp_async16(wAddr[nxt] + j * 16, Wgn + j * 4);
            }
            asm volatile("cp.async.commit_group;\n");
            asm volatile("cp.async.wait_group 1;\n");
        } else {
            asm volatile("cp.async.wait_group 0;\n");
        }
        __syncthreads();

        const uint32_t* As = Abuf[cur];
        const uint32_t* Ws = Wbuf[cur];
#pragma unroll
        for (int kk = 0; kk < 32; kk += 8) {
            uint32_t af[2][4];
#pragma unroll
            for (int mi = 0; mi < 2; mi++) {
                int r0 = (wm * 32 + mi * 16 + lr) * SMS + kk + lc;
                int r1 = r0 + 8 * SMS;
                af[mi][0] = As[r0];
                af[mi][1] = As[r1];
                af[mi][2] = As[r0 + 4];
                af[mi][3] = As[r1 + 4];
            }
#pragma unroll
            for (int ni = 0; ni < 8; ni++) {
                int nb = (wn * 64 + ni * 8 + lr) * SMS + kk + lc;
                uint32_t b0 = Ws[nb];
                uint32_t b1 = Ws[nb + 4];
                mma_tf32(acc[0][ni], af[0][0], af[0][1], af[0][2], af[0][3], b0, b1);
                mma_tf32(acc[1][ni], af[1][0], af[1][1], af[1][2], af[1][3], b0, b1);
            }
        }
        __syncthreads();
    }

#pragma unroll
    for (int ni = 0; ni < 8; ni++) {
        int col = bn + wn * 64 + ni * 8 + lc * 2;
        float bj0 = bias[col], bj1 = bias[col + 1];
#pragma unroll
        for (int mi = 0; mi < 2; mi++) {
            int row = bm + wm * 32 + mi * 16 + lr;
            float v0 = acc[mi][ni][0] + bj0;
            float v1 = acc[mi][ni][1] + bj1;
            float v2 = acc[mi][ni][2] + bj0;
            float v3 = acc[mi][ni][3] + bj1;
            if (RELU) {
                v0 = fmaxf(v0, 0.f); v1 = fmaxf(v1, 0.f);
                v2 = fmaxf(v2, 0.f); v3 = fmaxf(v3, 0.f);
            }
            *(float2*)(C + (size_t)row * N + col)       = make_float2(v0, v1);
            *(float2*)(C + (size_t)(row + 8) * N + col) = make_float2(v2, v3);
        }
    }
}
#define GEMM_SMEM (4 * STAGE_U32 * 4)

// ---------------- tensor-core self-attention (no-max softmax) --------------
// grid (QQ/128, B*NH), 256 threads (8 warps). Warp w owns query rows w*16..w*16+15.
// smem: PQ [128][68] (Q then P, per-warp-private rows), Ks [64][36], Vt [32][68].
#define ATT_PQ_OFF 0
#define ATT_KS_OFF (128 * 68)
#define ATT_VT_OFF (128 * 68 + 64 * 36)
#define ATT_SMEM_U32 (128 * 68 + 64 * 36 + 32 * 68)
#define ATT_SMEM_BYTES (ATT_SMEM_U32 * 4)

__global__ __launch_bounds__(256, 2)
void attn_tc(const float* __restrict__ Qm, int ldq,
             const float* __restrict__ Km, int ldk,
             const float* __restrict__ Vm, int ldv,
             float* __restrict__ Om) {
    extern __shared__ uint32_t asm_[];
    uint32_t* PQ = asm_ + ATT_PQ_OFF;
    uint32_t* Ks = asm_ + ATT_KS_OFF;
    uint32_t* Vt = asm_ + ATT_VT_OFF;

    const int bh = blockIdx.y;
    const int b = bh / NHH, h = bh % NHH;
    const int q0 = blockIdx.x * 128;
    const int tid = threadIdx.x;
    const int warp = tid >> 5;
    const int lane = tid & 31;
    const int lr = lane >> 2;
    const int lc = lane & 3;
    const int m0 = warp * 16;
    const float scale = 0.17677669529663687f;

    // stage Q (scaled), all 128 rows cooperatively
    {
        const int lrow = tid >> 1, lhalf = (tid & 1) * 16;
        const float* qp = Qm + (size_t)(b * QQ + q0 + lrow) * ldq + h * DHH + lhalf;
#pragma unroll
        for (int j = 0; j < 16; j++)
            PQ[lrow * 68 + lhalf + j] = __float_as_uint(qp[j] * scale);
    }
    __syncthreads();

    // Q fragments (this warp's 16 rows), kept in registers all kernel
    uint32_t qf[4][4];
#pragma unroll
    for (int kb = 0; kb < 4; kb++) {
        int r0 = (m0 + lr) * 68 + kb * 8 + lc;
        int r1 = (m0 + 8 + lr) * 68 + kb * 8 + lc;
        qf[kb][0] = PQ[r0];
        qf[kb][1] = PQ[r1];
        qf[kb][2] = PQ[r0 + 4];
        qf[kb][3] = PQ[r1 + 4];
    }
    __syncthreads();   // everyone done reading Q before PQ is reused as P

    float acc_o[4][4];
#pragma unroll
    for (int ni = 0; ni < 4; ni++)
#pragma unroll
        for (int t = 0; t < 4; t++) acc_o[ni][t] = 0.f;
    float rs0 = 0.f, rs1 = 0.f;

    for (int kt = 0; kt < QQ; kt += 64) {
        // stage K tile [64][32] (stride 36) and V tile transposed [32 dh][64 key] (stride 68)
        {
            int idx = tid * 8;
            int kr = idx >> 5;          // 0..63
            int kc = idx & 31;          // 0,8,16,24
            const float* kp = Km + (size_t)(b * QQ + kt + kr) * ldk + h * DHH + kc;
            const float* vp = Vm + (size_t)(b * QQ + kt + kr) * ldv + h * DHH + kc;
#pragma unroll
            for (int j = 0; j < 8; j++) Ks[kr * 36 + kc + j] = __float_as_uint(kp[j]);
#pragma unroll
            for (int j = 0; j < 8; j++) Vt[(kc + j) * 68 + kr] = __float_as_uint(vp[j]);
        }
        __syncthreads();

        // S = Q @ K^T  (per-warp 16x64)
        float accs[8][4];
#pragma unroll
        for (int ni = 0; ni < 8; ni++) {
#pragma unroll
            for (int t = 0; t < 4; t++) accs[ni][t] = 0.f;
        }
#pragma unroll
        for (int kb = 0; kb < 4; kb++) {
#pragma unroll
            for (int ni = 0; ni < 8; ni++) {
                int nb = (ni * 8 + lr) * 36 + kb * 8 + lc;
                uint32_t b0 = Ks[nb];
                uint32_t b1 = Ks[nb + 4];
                mma_tf32(accs[ni], qf[kb][0], qf[kb][1], qf[kb][2], qf[kb][3], b0, b1);
            }
        }

        // P = exp(S); row sums; stage P into this warp's private PQ rows
#pragma unroll
        for (int ni = 0; ni < 8; ni++) {
            float p0 = __expf(accs[ni][0]);
            float p1 = __expf(accs[ni][1]);
            float p2 = __expf(accs[ni][2]);
            float p3 = __expf(accs[ni][3]);
            rs0 += p0 + p1;
            rs1 += p2 + p3;
            int c0 = (m0 + lr) * 68 + ni * 8 + 2 * lc;
            int c1 = (m0 + 8 + lr) * 68 + ni * 8 + 2 * lc;
            PQ[c0]     = __float_as_uint(p0);
            PQ[c0 + 1] = __float_as_uint(p1);
            PQ[c1]     = __float_as_uint(p2);
            PQ[c1 + 1] = __float_as_uint(p3);
        }
        __syncwarp();

        // O += P @ V   (per-warp 16x32, k=64)
#pragma unroll
        for (int kb = 0; kb < 8; kb++) {
            int r0 = (m0 + lr) * 68 + kb * 8 + lc;
            int r1 = (m0 + 8 + lr) * 68 + kb * 8 + lc;
            uint32_t a0 = PQ[r0];
            uint32_t a1 = PQ[r1];
            uint32_t a2 = PQ[r0 + 4];
            uint32_t a3 = PQ[r1 + 4];
#pragma unroll
            for (int ni = 0; ni < 4; ni++) {
                int nb = (ni * 8 + lr) * 68 + kb * 8 + lc;
                uint32_t b0 = Vt[nb];
                uint32_t b1 = Vt[nb + 4];
                mma_tf32(acc_o[ni], a0, a1, a2, a3, b0, b1);
            }
        }
        __syncthreads();   // before next tile overwrites Ks/Vt
    }

    // reduce row sums across the 4 lanes sharing a row (lane = lr*4+lc)
    rs0 += __shfl_xor_sync(0xffffffff, rs0, 1);
    rs0 += __shfl_xor_sync(0xffffffff, rs0, 2);
    rs1 += __shfl_xor_sync(0xffffffff, rs1, 1);
    rs1 += __shfl_xor_sync(0xffffffff, rs1, 2);
    float inv0 = 1.f / rs0;
    float inv1 = 1.f / rs1;

#pragma unroll
    for (int ni = 0; ni < 4; ni++) {
        int col = h * DHH + ni * 8 + 2 * lc;
        size_t row0 = (size_t)(b * QQ + q0 + m0 + lr) * EE + col;
        size_t row1 = (size_t)(b * QQ + q0 + m0 + 8 + lr) * EE + col;
        *(float2*)(Om + row0) = make_float2(acc_o[ni][0] * inv0, acc_o[ni][1] * inv0);
        *(float2*)(Om + row1) = make_float2(acc_o[ni][2] * inv1, acc_o[ni][3] * inv1);
    }
}

// ---------------- residual add + LayerNorm (rows of 256) ----------------
__global__ void addln_kernel(const float* __restrict__ X, const float* __restrict__ Y,
                             const float* __restrict__ gam, const float* __restrict__ bet,
                             float* __restrict__ out) {
    int row = blockIdx.x;
    int t = threadIdx.x;
    size_t base = (size_t)row * EE;
    float x = X[base + t] + Y[base + t];

    __shared__ float red[8];
    __shared__ float mu_s, rstd_s;

    float s = x;
#pragma unroll
    for (int o = 16; o > 0; o >>= 1) s += __shfl_down_sync(0xffffffff, s, o);
    if ((t & 31) == 0) red[t >> 5] = s;
    __syncthreads();
    if (t == 0) {
        float tot = 0.f;
#pragma unroll
        for (int i = 0; i < 8; i++) tot += red[i];
        mu_s = tot * (1.f / EE);
    }
    __syncthreads();
    float mu = mu_s;
    float d = x - mu;
    float s2 = d * d;
#pragma unroll
    for (int o = 16; o > 0; o >>= 1) s2 += __shfl_down_sync(0xffffffff, s2, o);
    if ((t & 31) == 0) red[t >> 5] = s2;
    __syncthreads();
    if (t == 0) {
        float tot = 0.f;
#pragma unroll
        for (int i = 0; i < 8; i++) tot += red[i];
        rstd_s = rsqrtf(tot * (1.f / EE) + 1e-5f);
    }
    __syncthreads();
    out[base + t] = (x - mu) * rstd_s * gam[t] + bet[t];
}

// ---------------- attention-weight softmax over L*P=16 ----------------
__global__ void awsm_kernel(float* __restrict__ aw) {
    int i = blockIdx.x * blockDim.x + threadIdx.x;
    if (i >= BB * QQ * NHH) return;
    float* p = aw + (size_t)i * 16;
    float v[16];
    float m = -1e30f;
#pragma unroll
    for (int j = 0; j < 16; j++) { v[j] = p[j]; m = fmaxf(m, v[j]); }
    float s = 0.f;
#pragma unroll
    for (int j = 0; j < 16; j++) { v[j] = __expf(v[j] - m); s += v[j]; }
    float inv = 1.f / s;
#pragma unroll
    for (int j = 0; j < 16; j++) p[j] = v[j] * inv;
}

// ---------------- deformable bilinear sampling ----------------
__device__ __forceinline__ float fetch_corner(const float* __restrict__ vb,
                                              float yi, float xi, int Hl, int Wl) {
    bool valid = (xi >= 0.f) && (xi <= (float)(Wl - 1)) &&
                 (yi >= 0.f) && (yi <= (float)(Hl - 1));
    int xc = (int)fminf(fmaxf(xi, 0.f), (float)(Wl - 1));
    int yc = (int)fminf(fmaxf(yi, 0.f), (float)(Hl - 1));
    float v = vb[(size_t)(yc * Wl + xc) * EE];
    return valid ? v : 0.f;
}

__global__ void sample_kernel(const float* __restrict__ refp, const float* __restrict__ off,
                              const float* __restrict__ aw, const float* __restrict__ val,
                              float* __restrict__ out) {
    int wg = (blockIdx.x * blockDim.x + threadIdx.x) >> 5;
    int lane = threadIdx.x & 31;
    if (wg >= BB * QQ * NHH) return;
    int h = wg % NHH;
    int bq = wg / NHH;
    int b = bq / QQ;

    const float* rp = refp + (size_t)bq * (LLV * 2);
    const float* op = off + (size_t)bq * 256 + h * 32;
    const float* ap = aw + (size_t)bq * 128 + h * 16;

    const int Hs[4] = {128, 64, 32, 16};
    const int Ws2[4] = {128, 64, 32, 16};
    const int S0[4] = {0, 16384, 20480, 21504};

    float acc = 0.f;
#pragma unroll
    for (int l = 0; l < 4; l++) {
        int Hi = Hs[l], Wi = Ws2[l];
        float Hl = (float)Hi, Wl = (float)Wi;
        const float* vb = val + ((size_t)b * STOT + S0[l]) * EE + h * 32 + lane;
        float rx = rp[l * 2 + 0], ry = rp[l * 2 + 1];
#pragma unroll
        for (int p = 0; p < 4; p++) {
            float ox = op[l * 8 + p * 2 + 0];
            float oy = op[l * 8 + p * 2 + 1];
            float a = ap[l * 4 + p];
            float x = fmaf(rx, Wl, ox) - 0.5f;
            float y = fmaf(ry, Hl, oy) - 0.5f;
            float x0 = floorf(x), y0 = floorf(y);
            float wx = x - x0, wy = y - y0;
            float sum = 0.f;
            sum += fetch_corner(vb, y0,       x0,       Hi, Wi) * (1.f - wy) * (1.f - wx);
            sum += fetch_corner(vb, y0,       x0 + 1.f, Hi, Wi) * (1.f - wy) * wx;
            sum += fetch_corner(vb, y0 + 1.f, x0,       Hi, Wi) * wy * (1.f - wx);
            sum += fetch_corner(vb, y0 + 1.f, x0 + 1.f, Hi, Wi) * wy * wx;
            acc = fmaf(a, sum, acc);
        }
    }
    out[(size_t)bq * EE + h * 32 + lane] = acc;
}

// ---------------- launch ----------------
extern "C" void kernel_launch(void* const* d_in, const int* in_sizes, int n_in,
                              void* d_out, int out_size) {
    const float* tgt   = (const float*)d_in[0];
    const float* qpos  = (const float*)d_in[1];
    const float* refp  = (const float*)d_in[2];
    const float* src   = (const float*)d_in[3];
    const float* ipw   = (const float*)d_in[6];
    const float* ipb   = (const float*)d_in[7];
    const float* outpw = (const float*)d_in[8];
    const float* outpb = (const float*)d_in[9];
    const float* n1g   = (const float*)d_in[10];
    const float* n1b   = (const float*)d_in[11];
    const float* offw  = (const float*)d_in[12];
    const float* offb  = (const float*)d_in[13];
    const float* aww   = (const float*)d_in[14];
    const float* awb   = (const float*)d_in[15];
    const float* vpw   = (const float*)d_in[16];
    const float* vpb   = (const float*)d_in[17];
    const float* opw   = (const float*)d_in[18];
    const float* opb   = (const float*)d_in[19];
    const float* n2g   = (const float*)d_in[20];
    const float* n2b   = (const float*)d_in[21];
    const float* w1    = (const float*)d_in[22];
    const float* b1    = (const float*)d_in[23];
    const float* w2    = (const float*)d_in[24];
    const float* b2    = (const float*)d_in[25];
    const float* n3g   = (const float*)d_in[26];
    const float* n3b   = (const float*)d_in[27];
    float* out = (float*)d_out;

    float *qk, *qk2, *v, *ctx, *tmp, *tgt1, *query, *value, *off, *aw, *samp, *tgt2, *ffn1;
    cudaGetSymbolAddress((void**)&qk,    g_qk);
    cudaGetSymbolAddress((void**)&qk2,   g_qk2);
    cudaGetSymbolAddress((void**)&v,     g_v);
    cudaGetSymbolAddress((void**)&ctx,   g_ctx);
    cudaGetSymbolAddress((void**)&tmp,   g_tmp);
    cudaGetSymbolAddress((void**)&tgt1,  g_tgt1);
    cudaGetSymbolAddress((void**)&query, g_query);
    cudaGetSymbolAddress((void**)&value, g_value);
    cudaGetSymbolAddress((void**)&off,   g_off);
    cudaGetSymbolAddress((void**)&aw,    g_aw);
    cudaGetSymbolAddress((void**)&samp,  g_samp);
    cudaGetSymbolAddress((void**)&tgt2,  g_tgt2);
    cudaGetSymbolAddress((void**)&ffn1,  g_ffn1);

    cudaFuncSetAttribute(gemm_tc<0>, cudaFuncAttributeMaxDynamicSharedMemorySize, GEMM_SMEM);
    cudaFuncSetAttribute(gemm_tc<1>, cudaFuncAttributeMaxDynamicSharedMemorySize, GEMM_SMEM);
    cudaFuncSetAttribute(attn_tc,    cudaFuncAttributeMaxDynamicSharedMemorySize, ATT_SMEM_BYTES);

    const int M = BB * QQ;          // 8192
    const int n_el = M * EE;

    // 1) qk = tgt + query_pos
    add_kernel<<<(n_el / 4 + 255) / 256, 256>>>((const float4*)tgt, (const float4*)qpos,
                                                (float4*)qk, n_el / 4);

    // 2) merged q|k projection (N=512) + v projection
    gemm_tc<0><<<dim3(4, M / 128), 256, GEMM_SMEM>>>(qk,  ipw,             ipb,       qk2, M, 512, 256);
    gemm_tc<0><<<dim3(2, M / 128), 256, GEMM_SMEM>>>(tgt, ipw + 512 * 256, ipb + 512, v,   M, 256, 256);

    // 3) self-attention (tensor cores)
    attn_tc<<<dim3(QQ / 128, BB * NHH), 256, ATT_SMEM_BYTES>>>(qk2, 512, qk2 + 256, 512, v, 256, ctx);

    // 4) out projection + LN1
    gemm_tc<0><<<dim3(2, M / 128), 256, GEMM_SMEM>>>(ctx, outpw, outpb, tmp, M, 256, 256);
    addln_kernel<<<M, 256>>>(tgt, tmp, n1g, n1b, tgt1);

    // 5) query = tgt1 + query_pos
    add_kernel<<<(n_el / 4 + 255) / 256, 256>>>((const float4*)tgt1, (const float4*)qpos,
                                                (float4*)query, n_el / 4);

    // 6) value projection (174080 x 256 x 256)
    gemm_tc<0><<<dim3(2, (BB * STOT) / 128), 256, GEMM_SMEM>>>(src, vpw, vpb, value, BB * STOT, 256, 256);

    // 7) offsets + attention weights
    gemm_tc<0><<<dim3(2, M / 128), 256, GEMM_SMEM>>>(query, offw, offb, off, M, 256, 256);
    gemm_tc<0><<<dim3(1, M / 128), 256, GEMM_SMEM>>>(query, aww, awb, aw, M, 128, 256);
    awsm_kernel<<<(BB * QQ * NHH + 255) / 256, 256>>>(aw);

    // 8) deformable sampling
    sample_kernel<<<(BB * QQ * NHH) / 8, 256>>>(refp, off, aw, value, samp);

    // 9) output projection + LN2
    gemm_tc<0><<<dim3(2, M / 128), 256, GEMM_SMEM>>>(samp, opw, opb, tmp, M, 256, 256);
    addln_kernel<<<M, 256>>>(tgt1, tmp, n2g, n2b, tgt2);

    // 10) FFN + LN3
    gemm_tc<1><<<dim3(8, M / 128), 256, GEMM_SMEM>>>(tgt2, w1, b1, ffn1, M, 1024, 256);
    gemm_tc<0><<<dim3(2, M / 128), 256, GEMM_SMEM>>>(ffn1, w2, b2, tmp, M, 256, 1024);
    addln_kernel<<<M, 256>>>(tgt2, tmp, n3g, n3b, out);
}

// round 5
// speedup vs baseline: 1.6472x; 1.3517x over previous
#include <cuda_runtime.h>
#include <math.h>
#include <stdint.h>

#define BB   8
#define QQ   1024
#define EE   256
#define NHH  8
#define DHH  32
#define LLV  4
#define PPV  4
#define STOT 21760

// ---------------- scratch (device globals: allocation-free) ----------------
__device__ float g_qk   [BB*QQ*EE];
__device__ float g_qk2  [BB*QQ*512];
__device__ float g_v    [BB*QQ*EE];
__device__ float g_ctx  [BB*QQ*EE];
__device__ float g_tmp  [BB*QQ*EE];
__device__ float g_tgt1 [BB*QQ*EE];
__device__ float g_query[BB*QQ*EE];
__device__ float g_value[(size_t)BB*STOT*EE];
__device__ float g_off  [BB*QQ*EE];
__device__ float g_aw   [BB*QQ*128];
__device__ float g_samp [BB*QQ*EE];
__device__ float g_tgt2 [BB*QQ*EE];
__device__ float g_ffn1 [BB*QQ*4*EE];

// ---------------- elementwise add (vectorized) ----------------
__global__ void add_kernel(const float4* __restrict__ a, const float4* __restrict__ b,
                           float4* __restrict__ c, int n4) {
    int i = blockIdx.x * blockDim.x + threadIdx.x;
    if (i < n4) {
        float4 x = a[i], y = b[i];
        c[i] = make_float4(x.x + y.x, x.y + y.y, x.z + y.z, x.w + y.w);
    }
}

// ---------------- mma / ldmatrix helpers ----------------
__device__ __forceinline__ void mma_tf32(float* c,
                                         uint32_t a0, uint32_t a1, uint32_t a2, uint32_t a3,
                                         uint32_t b0, uint32_t b1) {
    asm volatile("mma.sync.aligned.m16n8k8.row.col.f32.tf32.tf32.f32 "
                 "{%0,%1,%2,%3}, {%4,%5,%6,%7}, {%8,%9}, {%0,%1,%2,%3};\n"
                 : "+f"(c[0]), "+f"(c[1]), "+f"(c[2]), "+f"(c[3])
                 : "r"(a0), "r"(a1), "r"(a2), "r"(a3), "r"(b0), "r"(b1));
}

__device__ __forceinline__ void ldsm_x4(uint32_t* r, uint32_t addr) {
    asm volatile("ldmatrix.sync.aligned.m8n8.x4.shared.b16 {%0,%1,%2,%3}, [%4];\n"
                 : "=r"(r[0]), "=r"(r[1]), "=r"(r[2]), "=r"(r[3]) : "r"(addr));
}

__device__ __forceinline__ void cp_async16(uint32_t smem_addr, const void* gmem) {
    asm volatile("cp.async.ca.shared.global [%0], [%1], 16;\n" :: "r"(smem_addr), "l"(gmem));
}

// ---------------- tensor-core GEMM (cp.async double-buffer + ldmatrix) -----
// C[M,N] = A[M,K] @ W[N,K]^T + bias.  128x128 tile, 256 thr (8 warps 4m x 2n).
#define SMS 36
#define STAGE_U32 (128 * SMS)
template<int RELU>
__global__ __launch_bounds__(256, 1)
void gemm_tc(const float* __restrict__ A, const float* __restrict__ W,
             const float* __restrict__ bias, float* __restrict__ C,
             int M, int N, int K) {
    extern __shared__ uint32_t sm[];
    uint32_t* Abuf[2] = { sm,                sm + STAGE_U32 };
    uint32_t* Wbuf[2] = { sm + 2*STAGE_U32,  sm + 3*STAGE_U32 };

    const int bm = blockIdx.y * 128;
    const int bn = blockIdx.x * 128;
    const int tid  = threadIdx.x;
    const int warp = tid >> 5;
    const int lane = tid & 31;
    const int wm = warp >> 1;
    const int wn = warp & 1;
    const int lr = lane >> 2;
    const int lc = lane & 3;

    // ldmatrix lane->address offsets
    const int arow = (lane & 7) + ((lane >> 3) & 1) * 8;   // A: row within m16
    const int acol = (lane >> 4) * 4;                      // A: k quadrant
    const int brow = (lane & 7) + (lane >> 4) * 8;         // B: n row (2 frags)
    const int bcol = ((lane >> 3) & 1) * 4;                // B: k quadrant

    uint32_t aOff[2], bOff[4];
#pragma unroll
    for (int mi = 0; mi < 2; mi++)
        aOff[mi] = ((wm * 32 + mi * 16 + arow) * SMS + acol) * 4;
#pragma unroll
    for (int p = 0; p < 4; p++)
        bOff[p] = ((wn * 64 + p * 16 + brow) * SMS + bcol) * 4;

    uint32_t AsmA[2], WsmA[2];
#pragma unroll
    for (int s = 0; s < 2; s++) {
        AsmA[s] = (uint32_t)__cvta_generic_to_shared(Abuf[s]);
        WsmA[s] = (uint32_t)__cvta_generic_to_shared(Wbuf[s]);
    }

    float acc[2][8][4];
#pragma unroll
    for (int mi = 0; mi < 2; mi++)
#pragma unroll
        for (int ni = 0; ni < 8; ni++)
#pragma unroll
            for (int t = 0; t < 4; t++) acc[mi][ni][t] = 0.f;

    const int lrow  = tid >> 1;
    const int lhalf = (tid & 1) * 16;
    const float* Ag = A + (size_t)(bm + lrow) * K + lhalf;
    const float* Wg = W + (size_t)(bn + lrow) * K + lhalf;

    uint32_t aStAddr[2], wStAddr[2];
#pragma unroll
    for (int s = 0; s < 2; s++) {
        aStAddr[s] = AsmA[s] + (lrow * SMS + lhalf) * 4;
        wStAddr[s] = WsmA[s] + (lrow * SMS + lhalf) * 4;
    }

    const int nch = K >> 5;

#pragma unroll
    for (int j = 0; j < 4; j++) {
        cp_async16(aStAddr[0] + j * 16, Ag + j * 4);
        cp_async16(wStAddr[0] + j * 16, Wg + j * 4);
    }
    asm volatile("cp.async.commit_group;\n");

    for (int c = 0; c < nch; c++) {
        const int cur = c & 1;
        if (c + 1 < nch) {
            const float* Agn = Ag + (size_t)(c + 1) * 32;
            const float* Wgn = Wg + (size_t)(c + 1) * 32;
            const int nxt = cur ^ 1;
#pragma unroll
            for (int j = 0; j < 4; j++) {
                cp_async16(aStAddr[nxt] + j * 16, Agn + j * 4);
                cp_async16(wStAddr[nxt] + j * 16, Wgn + j * 4);
            }
            asm volatile("cp.async.commit_group;\n");
            asm volatile("cp.async.wait_group 1;\n");
        } else {
            asm volatile("cp.async.wait_group 0;\n");
        }
        __syncthreads();

        const uint32_t aS = AsmA[cur];
        const uint32_t wS = WsmA[cur];
#pragma unroll
        for (int kk = 0; kk < 32; kk += 8) {
            uint32_t a0[4], a1[4];
            ldsm_x4(a0, aS + aOff[0] + kk * 4);
            ldsm_x4(a1, aS + aOff[1] + kk * 4);
#pragma unroll
            for (int p = 0; p < 4; p++) {
                uint32_t bf[4];
                ldsm_x4(bf, wS + bOff[p] + kk * 4);
                mma_tf32(acc[0][2*p],   a0[0], a0[1], a0[2], a0[3], bf[0], bf[1]);
                mma_tf32(acc[1][2*p],   a1[0], a1[1], a1[2], a1[3], bf[0], bf[1]);
                mma_tf32(acc[0][2*p+1], a0[0], a0[1], a0[2], a0[3], bf[2], bf[3]);
                mma_tf32(acc[1][2*p+1], a1[0], a1[1], a1[2], a1[3], bf[2], bf[3]);
            }
        }
        __syncthreads();
    }

#pragma unroll
    for (int ni = 0; ni < 8; ni++) {
        int col = bn + wn * 64 + ni * 8 + lc * 2;
        float bj0 = bias[col], bj1 = bias[col + 1];
#pragma unroll
        for (int mi = 0; mi < 2; mi++) {
            int row = bm + wm * 32 + mi * 16 + lr;
            float v0 = acc[mi][ni][0] + bj0;
            float v1 = acc[mi][ni][1] + bj1;
            float v2 = acc[mi][ni][2] + bj0;
            float v3 = acc[mi][ni][3] + bj1;
            if (RELU) {
                v0 = fmaxf(v0, 0.f); v1 = fmaxf(v1, 0.f);
                v2 = fmaxf(v2, 0.f); v3 = fmaxf(v3, 0.f);
            }
            *(float2*)(C + (size_t)row * N + col)       = make_float2(v0, v1);
            *(float2*)(C + (size_t)(row + 8) * N + col) = make_float2(v2, v3);
        }
    }
}
#define GEMM_SMEM (4 * STAGE_U32 * 4)

// ---------------- tensor-core self-attention (ldmatrix everywhere) ---------
#define ATT_PQ_OFF 0
#define ATT_KS_OFF (128 * 68)
#define ATT_VT_OFF (128 * 68 + 64 * 36)
#define ATT_SMEM_U32 (128 * 68 + 64 * 36 + 32 * 68)
#define ATT_SMEM_BYTES (ATT_SMEM_U32 * 4)

__global__ __launch_bounds__(256, 2)
void attn_tc(const float* __restrict__ Qm, int ldq,
             const float* __restrict__ Km, int ldk,
             const float* __restrict__ Vm, int ldv,
             float* __restrict__ Om) {
    extern __shared__ uint32_t asm_[];
    uint32_t* PQ = asm_ + ATT_PQ_OFF;
    uint32_t* Ks = asm_ + ATT_KS_OFF;
    uint32_t* Vt = asm_ + ATT_VT_OFF;
    const uint32_t pqA = (uint32_t)__cvta_generic_to_shared(PQ);
    const uint32_t ksA = (uint32_t)__cvta_generic_to_shared(Ks);
    const uint32_t vtA = (uint32_t)__cvta_generic_to_shared(Vt);

    const int bh = blockIdx.y;
    const int b = bh / NHH, h = bh % NHH;
    const int q0 = blockIdx.x * 128;
    const int tid = threadIdx.x;
    const int warp = tid >> 5;
    const int lane = tid & 31;
    const int lr = lane >> 2;
    const int lc = lane & 3;
    const int m0 = warp * 16;
    const float scale = 0.17677669529663687f;

    const int arow = (lane & 7) + ((lane >> 3) & 1) * 8;
    const int acol = (lane >> 4) * 4;
    const int brow = (lane & 7) + (lane >> 4) * 8;
    const int bcol = ((lane >> 3) & 1) * 4;

    const uint32_t pOffA = pqA + ((m0 + arow) * 68 + acol) * 4;   // A-frag base in PQ

    // stage Q (scaled)
    {
        const int lrow = tid >> 1, lhalf = (tid & 1) * 16;
        const float* qp = Qm + (size_t)(b * QQ + q0 + lrow) * ldq + h * DHH + lhalf;
#pragma unroll
        for (int j = 0; j < 16; j++)
            PQ[lrow * 68 + lhalf + j] = __float_as_uint(qp[j] * scale);
    }
    __syncthreads();

    uint32_t qf[4][4];
#pragma unroll
    for (int kb = 0; kb < 4; kb++)
        ldsm_x4(qf[kb], pOffA + kb * 32);
    __syncthreads();

    float acc_o[4][4];
#pragma unroll
    for (int ni = 0; ni < 4; ni++)
#pragma unroll
        for (int t = 0; t < 4; t++) acc_o[ni][t] = 0.f;
    float rs0 = 0.f, rs1 = 0.f;

    for (int kt = 0; kt < QQ; kt += 64) {
        // stage K [64][32] (stride 36), V transposed [32][64] (stride 68)
        {
            int idx = tid * 8;
            int kr = idx >> 5;
            int kc = idx & 31;
            const float* kp = Km + (size_t)(b * QQ + kt + kr) * ldk + h * DHH + kc;
            const float* vp = Vm + (size_t)(b * QQ + kt + kr) * ldv + h * DHH + kc;
            float4 k0 = *(const float4*)kp;
            float4 k1 = *(const float4*)(kp + 4);
            float4 v0 = *(const float4*)vp;
            float4 v1 = *(const float4*)(vp + 4);
            uint32_t* kd = Ks + kr * 36 + kc;
            kd[0] = __float_as_uint(k0.x); kd[1] = __float_as_uint(k0.y);
            kd[2] = __float_as_uint(k0.z); kd[3] = __float_as_uint(k0.w);
            kd[4] = __float_as_uint(k1.x); kd[5] = __float_as_uint(k1.y);
            kd[6] = __float_as_uint(k1.z); kd[7] = __float_as_uint(k1.w);
            uint32_t* vd = Vt + kc * 68 + kr;
            vd[0*68] = __float_as_uint(v0.x); vd[1*68] = __float_as_uint(v0.y);
            vd[2*68] = __float_as_uint(v0.z); vd[3*68] = __float_as_uint(v0.w);
            vd[4*68] = __float_as_uint(v1.x); vd[5*68] = __float_as_uint(v1.y);
            vd[6*68] = __float_as_uint(v1.z); vd[7*68] = __float_as_uint(v1.w);
        }
        __syncthreads();

        // S = Q @ K^T (16x64 per warp)
        float accs[8][4];
#pragma unroll
        for (int ni = 0; ni < 8; ni++)
#pragma unroll
            for (int t = 0; t < 4; t++) accs[ni][t] = 0.f;
#pragma unroll
        for (int kb = 0; kb < 4; kb++) {
#pragma unroll
            for (int p = 0; p < 4; p++) {
                uint32_t bf[4];
                ldsm_x4(bf, ksA + ((p * 16 + brow) * 36 + kb * 8 + bcol) * 4);
                mma_tf32(accs[2*p],   qf[kb][0], qf[kb][1], qf[kb][2], qf[kb][3], bf[0], bf[1]);
                mma_tf32(accs[2*p+1], qf[kb][0], qf[kb][1], qf[kb][2], qf[kb][3], bf[2], bf[3]);
            }
        }

        // P = exp(S); row sums; store P (float2) into warp-private PQ rows
#pragma unroll
        for (int ni = 0; ni < 8; ni++) {
            float p0 = __expf(accs[ni][0]);
            float p1 = __expf(accs[ni][1]);
            float p2 = __expf(accs[ni][2]);
            float p3 = __expf(accs[ni][3]);
            rs0 += p0 + p1;
            rs1 += p2 + p3;
            int c0 = (m0 + lr) * 68 + ni * 8 + 2 * lc;
            int c1 = (m0 + 8 + lr) * 68 + ni * 8 + 2 * lc;
            *(float2*)(PQ + c0) = make_float2(p0, p1);
            *(float2*)(PQ + c1) = make_float2(p2, p3);
        }
        __syncwarp();

        // O += P @ V (16x32 per warp, k=64)
#pragma unroll
        for (int kb = 0; kb < 8; kb++) {
            uint32_t af[4];
            ldsm_x4(af, pOffA + kb * 32);
#pragma unroll
            for (int p = 0; p < 2; p++) {
                uint32_t bf[4];
                ldsm_x4(bf, vtA + ((p * 16 + brow) * 68 + kb * 8 + bcol) * 4);
                mma_tf32(acc_o[2*p],   af[0], af[1], af[2], af[3], bf[0], bf[1]);
                mma_tf32(acc_o[2*p+1], af[0], af[1], af[2], af[3], bf[2], bf[3]);
            }
        }
        __syncthreads();
    }

    rs0 += __shfl_xor_sync(0xffffffff, rs0, 1);
    rs0 += __shfl_xor_sync(0xffffffff, rs0, 2);
    rs1 += __shfl_xor_sync(0xffffffff, rs1, 1);
    rs1 += __shfl_xor_sync(0xffffffff, rs1, 2);
    float inv0 = 1.f / rs0;
    float inv1 = 1.f / rs1;

#pragma unroll
    for (int ni = 0; ni < 4; ni++) {
        int col = h * DHH + ni * 8 + 2 * lc;
        size_t row0 = (size_t)(b * QQ + q0 + m0 + lr) * EE + col;
        size_t row1 = (size_t)(b * QQ + q0 + m0 + 8 + lr) * EE + col;
        *(float2*)(Om + row0) = make_float2(acc_o[ni][0] * inv0, acc_o[ni][1] * inv0);
        *(float2*)(Om + row1) = make_float2(acc_o[ni][2] * inv1, acc_o[ni][3] * inv1);
    }
}

// ---------------- residual add + LayerNorm (rows of 256) ----------------
__global__ void addln_kernel(const float* __restrict__ X, const float* __restrict__ Y,
                             const float* __restrict__ gam, const float* __restrict__ bet,
                             float* __restrict__ out) {
    int row = blockIdx.x;
    int t = threadIdx.x;
    size_t base = (size_t)row * EE;
    float x = X[base + t] + Y[base + t];

    __shared__ float red[8];
    __shared__ float mu_s, rstd_s;

    float s = x;
#pragma unroll
    for (int o = 16; o > 0; o >>= 1) s += __shfl_down_sync(0xffffffff, s, o);
    if ((t & 31) == 0) red[t >> 5] = s;
    __syncthreads();
    if (t == 0) {
        float tot = 0.f;
#pragma unroll
        for (int i = 0; i < 8; i++) tot += red[i];
        mu_s = tot * (1.f / EE);
    }
    __syncthreads();
    float mu = mu_s;
    float d = x - mu;
    float s2 = d * d;
#pragma unroll
    for (int o = 16; o > 0; o >>= 1) s2 += __shfl_down_sync(0xffffffff, s2, o);
    if ((t & 31) == 0) red[t >> 5] = s2;
    __syncthreads();
    if (t == 0) {
        float tot = 0.f;
#pragma unroll
        for (int i = 0; i < 8; i++) tot += red[i];
        rstd_s = rsqrtf(tot * (1.f / EE) + 1e-5f);
    }
    __syncthreads();
    out[base + t] = (x - mu) * rstd_s * gam[t] + bet[t];
}

// ---------------- attention-weight softmax over L*P=16 ----------------
__global__ void awsm_kernel(float* __restrict__ aw) {
    int i = blockIdx.x * blockDim.x + threadIdx.x;
    if (i >= BB * QQ * NHH) return;
    float* p = aw + (size_t)i * 16;
    float v[16];
    float m = -1e30f;
#pragma unroll
    for (int j = 0; j < 16; j++) { v[j] = p[j]; m = fmaxf(m, v[j]); }
    float s = 0.f;
#pragma unroll
    for (int j = 0; j < 16; j++) { v[j] = __expf(v[j] - m); s += v[j]; }
    float inv = 1.f / s;
#pragma unroll
    for (int j = 0; j < 16; j++) p[j] = v[j] * inv;
}

// ---------------- deformable bilinear sampling ----------------
__device__ __forceinline__ float fetch_corner(const float* __restrict__ vb,
                                              float yi, float xi, int Hl, int Wl) {
    bool valid = (xi >= 0.f) && (xi <= (float)(Wl - 1)) &&
                 (yi >= 0.f) && (yi <= (float)(Hl - 1));
    int xc = (int)fminf(fmaxf(xi, 0.f), (float)(Wl - 1));
    int yc = (int)fminf(fmaxf(yi, 0.f), (float)(Hl - 1));
    float v = vb[(size_t)(yc * Wl + xc) * EE];
    return valid ? v : 0.f;
}

__global__ void sample_kernel(const float* __restrict__ refp, const float* __restrict__ off,
                              const float* __restrict__ aw, const float* __restrict__ val,
                              float* __restrict__ out) {
    int wg = (blockIdx.x * blockDim.x + threadIdx.x) >> 5;
    int lane = threadIdx.x & 31;
    if (wg >= BB * QQ * NHH) return;
    int h = wg % NHH;
    int bq = wg / NHH;
    int b = bq / QQ;

    const float* rp = refp + (size_t)bq * (LLV * 2);
    const float* op = off + (size_t)bq * 256 + h * 32;
    const float* ap = aw + (size_t)bq * 128 + h * 16;

    const int Hs[4] = {128, 64, 32, 16};
    const int Ws2[4] = {128, 64, 32, 16};
    const int S0[4] = {0, 16384, 20480, 21504};

    float acc = 0.f;
#pragma unroll
    for (int l = 0; l < 4; l++) {
        int Hi = Hs[l], Wi = Ws2[l];
        float Hl = (float)Hi, Wl = (float)Wi;
        const float* vb = val + ((size_t)b * STOT + S0[l]) * EE + h * 32 + lane;
        float rx = rp[l * 2 + 0], ry = rp[l * 2 + 1];
#pragma unroll
        for (int p = 0; p < 4; p++) {
            float ox = op[l * 8 + p * 2 + 0];
            float oy = op[l * 8 + p * 2 + 1];
            float a = ap[l * 4 + p];
            float x = fmaf(rx, Wl, ox) - 0.5f;
            float y = fmaf(ry, Hl, oy) - 0.5f;
            float x0 = floorf(x), y0 = floorf(y);
            float wx = x - x0, wy = y - y0;
            float sum = 0.f;
            sum += fetch_corner(vb, y0,       x0,       Hi, Wi) * (1.f - wy) * (1.f - wx);
            sum += fetch_corner(vb, y0,       x0 + 1.f, Hi, Wi) * (1.f - wy) * wx;
            sum += fetch_corner(vb, y0 + 1.f, x0,       Hi, Wi) * wy * (1.f - wx);
            sum += fetch_corner(vb, y0 + 1.f, x0 + 1.f, Hi, Wi) * wy * wx;
            acc = fmaf(a, sum, acc);
        }
    }
    out[(size_t)bq * EE + h * 32 + lane] = acc;
}

// ---------------- launch ----------------
extern "C" void kernel_launch(void* const* d_in, const int* in_sizes, int n_in,
                              void* d_out, int out_size) {
    const float* tgt   = (const float*)d_in[0];
    const float* qpos  = (const float*)d_in[1];
    const float* refp  = (const float*)d_in[2];
    const float* src   = (const float*)d_in[3];
    const float* ipw   = (const float*)d_in[6];
    const float* ipb   = (const float*)d_in[7];
    const float* outpw = (const float*)d_in[8];
    const float* outpb = (const float*)d_in[9];
    const float* n1g   = (const float*)d_in[10];
    const float* n1b   = (const float*)d_in[11];
    const float* offw  = (const float*)d_in[12];
    const float* offb  = (const float*)d_in[13];
    const float* aww   = (const float*)d_in[14];
    const float* awb   = (const float*)d_in[15];
    const float* vpw   = (const float*)d_in[16];
    const float* vpb   = (const float*)d_in[17];
    const float* opw   = (const float*)d_in[18];
    const float* opb   = (const float*)d_in[19];
    const float* n2g   = (const float*)d_in[20];
    const float* n2b   = (const float*)d_in[21];
    const float* w1    = (const float*)d_in[22];
    const float* b1    = (const float*)d_in[23];
    const float* w2    = (const float*)d_in[24];
    const float* b2    = (const float*)d_in[25];
    const float* n3g   = (const float*)d_in[26];
    const float* n3b   = (const float*)d_in[27];
    float* out = (float*)d_out;

    float *qk, *qk2, *v, *ctx, *tmp, *tgt1, *query, *value, *off, *aw, *samp, *tgt2, *ffn1;
    cudaGetSymbolAddress((void**)&qk,    g_qk);
    cudaGetSymbolAddress((void**)&qk2,   g_qk2);
    cudaGetSymbolAddress((void**)&v,     g_v);
    cudaGetSymbolAddress((void**)&ctx,   g_ctx);
    cudaGetSymbolAddress((void**)&tmp,   g_tmp);
    cudaGetSymbolAddress((void**)&tgt1,  g_tgt1);
    cudaGetSymbolAddress((void**)&query, g_query);
    cudaGetSymbolAddress((void**)&value, g_value);
    cudaGetSymbolAddress((void**)&off,   g_off);
    cudaGetSymbolAddress((void**)&aw,    g_aw);
    cudaGetSymbolAddress((void**)&samp,  g_samp);
    cudaGetSymbolAddress((void**)&tgt2,  g_tgt2);
    cudaGetSymbolAddress((void**)&ffn1,  g_ffn1);

    cudaFuncSetAttribute(gemm_tc<0>, cudaFuncAttributeMaxDynamicSharedMemorySize, GEMM_SMEM);
    cudaFuncSetAttribute(gemm_tc<1>, cudaFuncAttributeMaxDynamicSharedMemorySize, GEMM_SMEM);
    cudaFuncSetAttribute(attn_tc,    cudaFuncAttributeMaxDynamicSharedMemorySize, ATT_SMEM_BYTES);

    const int M = BB * QQ;
    const int n_el = M * EE;

    add_kernel<<<(n_el / 4 + 255) / 256, 256>>>((const float4*)tgt, (const float4*)qpos,
                                                (float4*)qk, n_el / 4);

    gemm_tc<0><<<dim3(4, M / 128), 256, GEMM_SMEM>>>(qk,  ipw,             ipb,       qk2, M, 512, 256);
    gemm_tc<0><<<dim3(2, M / 128), 256, GEMM_SMEM>>>(tgt, ipw + 512 * 256, ipb + 512, v,   M, 256, 256);

    attn_tc<<<dim3(QQ / 128, BB * NHH), 256, ATT_SMEM_BYTES>>>(qk2, 512, qk2 + 256, 512, v, 256, ctx);

    gemm_tc<0><<<dim3(2, M / 128), 256, GEMM_SMEM>>>(ctx, outpw, outpb, tmp, M, 256, 256);
    addln_kernel<<<M, 256>>>(tgt, tmp, n1g, n1b, tgt1);

    add_kernel<<<(n_el / 4 + 255) / 256, 256>>>((const float4*)tgt1, (const float4*)qpos,
                                                (float4*)query, n_el / 4);

    gemm_tc<0><<<dim3(2, (BB * STOT) / 128), 256, GEMM_SMEM>>>(src, vpw, vpb, value, BB * STOT, 256, 256);

    gemm_tc<0><<<dim3(2, M / 128), 256, GEMM_SMEM>>>(query, offw, offb, off, M, 256, 256);
    gemm_tc<0><<<dim3(1, M / 128), 256, GEMM_SMEM>>>(query, aww, awb, aw, M, 128, 256);
    awsm_kernel<<<(BB * QQ * NHH + 255) / 256, 256>>>(aw);

    sample_kernel<<<(BB * QQ * NHH) / 8, 256>>>(refp, off, aw, value, samp);

    gemm_tc<0><<<dim3(2, M / 128), 256, GEMM_SMEM>>>(samp, opw, opb, tmp, M, 256, 256);
    addln_kernel<<<M, 256>>>(tgt1, tmp, n2g, n2b, tgt2);

    gemm_tc<1><<<dim3(8, M / 128), 256, GEMM_SMEM>>>(tgt2, w1, b1, ffn1, M, 1024, 256);
    gemm_tc<0><<<dim3(2, M / 128), 256, GEMM_SMEM>>>(ffn1, w2, b2, tmp, M, 256, 1024);
    addln_kernel<<<M, 256>>>(tgt2, tmp, n3g, n3b, out);
}

// round 6
// speedup vs baseline: 1.7426x; 1.0580x over previous
#include <cuda_runtime.h>
#include <math.h>
#include <stdint.h>

#define BB   8
#define QQ   1024
#define EE   256
#define NHH  8
#define DHH  32
#define LLV  4
#define PPV  4
#define STOT 21760

// ---------------- scratch (device globals: allocation-free) ----------------
__device__ float g_qk   [BB*QQ*EE];
__device__ float g_qk2  [BB*QQ*512];
__device__ float g_v    [BB*QQ*EE];
__device__ float g_ctx  [BB*QQ*EE];
__device__ float g_tmp  [BB*QQ*EE];
__device__ float g_tgt1 [BB*QQ*EE];
__device__ float g_query[BB*QQ*EE];
__device__ float g_value[(size_t)BB*STOT*EE];
__device__ float g_off  [BB*QQ*EE];
__device__ float g_aw   [BB*QQ*128];
__device__ float g_samp [BB*QQ*EE];
__device__ float g_tgt2 [BB*QQ*EE];
__device__ float g_ffn1 [BB*QQ*4*EE];

// ---------------- elementwise add (vectorized) ----------------
__global__ void add_kernel(const float4* __restrict__ a, const float4* __restrict__ b,
                           float4* __restrict__ c, int n4) {
    int i = blockIdx.x * blockDim.x + threadIdx.x;
    if (i < n4) {
        float4 x = a[i], y = b[i];
        c[i] = make_float4(x.x + y.x, x.y + y.y, x.z + y.z, x.w + y.w);
    }
}

// ---------------- mma / ldmatrix / cp.async helpers ----------------
__device__ __forceinline__ void mma_tf32(float* c,
                                         uint32_t a0, uint32_t a1, uint32_t a2, uint32_t a3,
                                         uint32_t b0, uint32_t b1) {
    asm volatile("mma.sync.aligned.m16n8k8.row.col.f32.tf32.tf32.f32 "
                 "{%0,%1,%2,%3}, {%4,%5,%6,%7}, {%8,%9}, {%0,%1,%2,%3};\n"
                 : "+f"(c[0]), "+f"(c[1]), "+f"(c[2]), "+f"(c[3])
                 : "r"(a0), "r"(a1), "r"(a2), "r"(a3), "r"(b0), "r"(b1));
}

__device__ __forceinline__ void ldsm_x4(uint32_t* r, uint32_t addr) {
    asm volatile("ldmatrix.sync.aligned.m8n8.x4.shared.b16 {%0,%1,%2,%3}, [%4];\n"
                 : "=r"(r[0]), "=r"(r[1]), "=r"(r[2]), "=r"(r[3]) : "r"(addr));
}

__device__ __forceinline__ void cp_async16(uint32_t smem_addr, const void* gmem) {
    asm volatile("cp.async.ca.shared.global [%0], [%1], 16;\n" :: "r"(smem_addr), "l"(gmem));
}

// ---------------- tensor-core GEMM (cp.async double-buffer + ldmatrix) -----
#define SMS 36
#define STAGE_U32 (128 * SMS)
template<int RELU>
__global__ __launch_bounds__(256, 2)
void gemm_tc(const float* __restrict__ A, const float* __restrict__ W,
             const float* __restrict__ bias, float* __restrict__ C,
             int M, int N, int K) {
    extern __shared__ uint32_t sm[];
    uint32_t* Abuf[2] = { sm,                sm + STAGE_U32 };
    uint32_t* Wbuf[2] = { sm + 2*STAGE_U32,  sm + 3*STAGE_U32 };

    const int bm = blockIdx.y * 128;
    const int bn = blockIdx.x * 128;
    const int tid  = threadIdx.x;
    const int warp = tid >> 5;
    const int lane = tid & 31;
    const int wm = warp >> 1;
    const int wn = warp & 1;
    const int lr = lane >> 2;
    const int lc = lane & 3;

    const int arow = (lane & 7) + ((lane >> 3) & 1) * 8;
    const int acol = (lane >> 4) * 4;
    const int brow = (lane & 7) + (lane >> 4) * 8;
    const int bcol = ((lane >> 3) & 1) * 4;

    uint32_t aOff[2], bOff[4];
#pragma unroll
    for (int mi = 0; mi < 2; mi++)
        aOff[mi] = ((wm * 32 + mi * 16 + arow) * SMS + acol) * 4;
#pragma unroll
    for (int p = 0; p < 4; p++)
        bOff[p] = ((wn * 64 + p * 16 + brow) * SMS + bcol) * 4;

    uint32_t AsmA[2], WsmA[2];
#pragma unroll
    for (int s = 0; s < 2; s++) {
        AsmA[s] = (uint32_t)__cvta_generic_to_shared(Abuf[s]);
        WsmA[s] = (uint32_t)__cvta_generic_to_shared(Wbuf[s]);
    }

    float acc[2][8][4];
#pragma unroll
    for (int mi = 0; mi < 2; mi++)
#pragma unroll
        for (int ni = 0; ni < 8; ni++)
#pragma unroll
            for (int t = 0; t < 4; t++) acc[mi][ni][t] = 0.f;

    const int lrow  = tid >> 1;
    const int lhalf = (tid & 1) * 16;
    const float* Ag = A + (size_t)(bm + lrow) * K + lhalf;
    const float* Wg = W + (size_t)(bn + lrow) * K + lhalf;

    uint32_t aStAddr[2], wStAddr[2];
#pragma unroll
    for (int s = 0; s < 2; s++) {
        aStAddr[s] = AsmA[s] + (lrow * SMS + lhalf) * 4;
        wStAddr[s] = WsmA[s] + (lrow * SMS + lhalf) * 4;
    }

    const int nch = K >> 5;

#pragma unroll
    for (int j = 0; j < 4; j++) {
        cp_async16(aStAddr[0] + j * 16, Ag + j * 4);
        cp_async16(wStAddr[0] + j * 16, Wg + j * 4);
    }
    asm volatile("cp.async.commit_group;\n");

    for (int c = 0; c < nch; c++) {
        const int cur = c & 1;
        if (c + 1 < nch) {
            const float* Agn = Ag + (size_t)(c + 1) * 32;
            const float* Wgn = Wg + (size_t)(c + 1) * 32;
            const int nxt = cur ^ 1;
#pragma unroll
            for (int j = 0; j < 4; j++) {
                cp_async16(aStAddr[nxt] + j * 16, Agn + j * 4);
                cp_async16(wStAddr[nxt] + j * 16, Wgn + j * 4);
            }
            asm volatile("cp.async.commit_group;\n");
            asm volatile("cp.async.wait_group 1;\n");
        } else {
            asm volatile("cp.async.wait_group 0;\n");
        }
        __syncthreads();

        const uint32_t aS = AsmA[cur];
        const uint32_t wS = WsmA[cur];
#pragma unroll
        for (int kk = 0; kk < 32; kk += 8) {
            uint32_t a0[4], a1[4];
            ldsm_x4(a0, aS + aOff[0] + kk * 4);
            ldsm_x4(a1, aS + aOff[1] + kk * 4);
#pragma unroll
            for (int p = 0; p < 4; p++) {
                uint32_t bf[4];
                ldsm_x4(bf, wS + bOff[p] + kk * 4);
                mma_tf32(acc[0][2*p],   a0[0], a0[1], a0[2], a0[3], bf[0], bf[1]);
                mma_tf32(acc[1][2*p],   a1[0], a1[1], a1[2], a1[3], bf[0], bf[1]);
                mma_tf32(acc[0][2*p+1], a0[0], a0[1], a0[2], a0[3], bf[2], bf[3]);
                mma_tf32(acc[1][2*p+1], a1[0], a1[1], a1[2], a1[3], bf[2], bf[3]);
            }
        }
        __syncthreads();
    }

#pragma unroll
    for (int ni = 0; ni < 8; ni++) {
        int col = bn + wn * 64 + ni * 8 + lc * 2;
        float bj0 = bias[col], bj1 = bias[col + 1];
#pragma unroll
        for (int mi = 0; mi < 2; mi++) {
            int row = bm + wm * 32 + mi * 16 + lr;
            float v0 = acc[mi][ni][0] + bj0;
            float v1 = acc[mi][ni][1] + bj1;
            float v2 = acc[mi][ni][2] + bj0;
            float v3 = acc[mi][ni][3] + bj1;
            if (RELU) {
                v0 = fmaxf(v0, 0.f); v1 = fmaxf(v1, 0.f);
                v2 = fmaxf(v2, 0.f); v3 = fmaxf(v3, 0.f);
            }
            *(float2*)(C + (size_t)row * N + col)       = make_float2(v0, v1);
            *(float2*)(C + (size_t)(row + 8) * N + col) = make_float2(v2, v3);
        }
    }
}
#define GEMM_SMEM (4 * STAGE_U32 * 4)

// ---------------- tensor-core self-attention ----------------
// PQ [128][68], Ks double-buffered [2][64][36], Vt [32][68] (single, reg-prefetched).
#define ATT_PQ_OFF  0
#define ATT_KS0_OFF (128 * 68)
#define ATT_KS1_OFF (128 * 68 + 64 * 36)
#define ATT_VT_OFF  (128 * 68 + 2 * 64 * 36)
#define ATT_SMEM_U32 (128 * 68 + 2 * 64 * 36 + 32 * 68)
#define ATT_SMEM_BYTES (ATT_SMEM_U32 * 4)

__global__ __launch_bounds__(256, 2)
void attn_tc(const float* __restrict__ Qm, int ldq,
             const float* __restrict__ Km, int ldk,
             const float* __restrict__ Vm, int ldv,
             float* __restrict__ Om) {
    extern __shared__ uint32_t asm_[];
    uint32_t* PQ = asm_ + ATT_PQ_OFF;
    uint32_t* Vt = asm_ + ATT_VT_OFF;
    const uint32_t pqA = (uint32_t)__cvta_generic_to_shared(PQ);
    const uint32_t vtA = (uint32_t)__cvta_generic_to_shared(Vt);
    uint32_t ksA[2];
    ksA[0] = (uint32_t)__cvta_generic_to_shared(asm_ + ATT_KS0_OFF);
    ksA[1] = (uint32_t)__cvta_generic_to_shared(asm_ + ATT_KS1_OFF);

    const int bh = blockIdx.y;
    const int b = bh / NHH, h = bh % NHH;
    const int q0 = blockIdx.x * 128;
    const int tid = threadIdx.x;
    const int warp = tid >> 5;
    const int lane = tid & 31;
    const int lr = lane >> 2;
    const int lc = lane & 3;
    const int m0 = warp * 16;
    const float scale = 0.17677669529663687f;

    const int arow = (lane & 7) + ((lane >> 3) & 1) * 8;
    const int acol = (lane >> 4) * 4;
    const int brow = (lane & 7) + (lane >> 4) * 8;
    const int bcol = ((lane >> 3) & 1) * 4;

    const uint32_t pOffA = pqA + ((m0 + arow) * 68 + acol) * 4;

    // K staging via cp.async: thread handles row=tid>>2, 2 16B segs
    const int krow = tid >> 2;
    const int kseg = (tid & 3) * 2;
    const float* kgBase = Km + (size_t)(b * QQ + krow) * ldk + h * DHH + kseg * 4;
    const uint32_t kstOff = (krow * 36 + kseg * 4) * 4;

    // V staging (permuted, conflict-free): c=tid&3, r=tid>>2
    const int vc = tid & 3;
    const int vr = tid >> 2;
    const int vkc = vc * 8;
    const int vkr = (vr + 8 * vc) & 63;
    const float* vgBase = Vm + (size_t)(b * QQ + vkr) * ldv + h * DHH + vkc;
    uint32_t* vtDst = Vt + vkc * 68 + vkr;

    // stage Q (scaled) + prologue loads for tile 0
    {
        const int lrow = tid >> 1, lhalf = (tid & 1) * 16;
        const float* qp = Qm + (size_t)(b * QQ + q0 + lrow) * ldq + h * DHH + lhalf;
#pragma unroll
        for (int j = 0; j < 16; j++)
            PQ[lrow * 68 + lhalf + j] = __float_as_uint(qp[j] * scale);
    }
    cp_async16(ksA[0] + kstOff,      kgBase);
    cp_async16(ksA[0] + kstOff + 16, kgBase + 4);
    asm volatile("cp.async.commit_group;\n");
    float4 vA = *(const float4*)vgBase;
    float4 vB = *(const float4*)(vgBase + 4);
    __syncthreads();

    uint32_t qf[4][4];
#pragma unroll
    for (int kb = 0; kb < 4; kb++)
        ldsm_x4(qf[kb], pOffA + kb * 32);

    // store V tile 0 (conflict-free scatter)
    vtDst[0*68] = __float_as_uint(vA.x); vtDst[1*68] = __float_as_uint(vA.y);
    vtDst[2*68] = __float_as_uint(vA.z); vtDst[3*68] = __float_as_uint(vA.w);
    vtDst[4*68] = __float_as_uint(vB.x); vtDst[5*68] = __float_as_uint(vB.y);
    vtDst[6*68] = __float_as_uint(vB.z); vtDst[7*68] = __float_as_uint(vB.w);
    asm volatile("cp.async.wait_group 0;\n");
    __syncthreads();

    float acc_o[4][4];
#pragma unroll
    for (int ni = 0; ni < 4; ni++)
#pragma unroll
        for (int t = 0; t < 4; t++) acc_o[ni][t] = 0.f;
    float rs0 = 0.f, rs1 = 0.f;

    const int NT = QQ / 64;
    for (int t = 0; t < NT; t++) {
        const int cur = t & 1;
        const bool more = (t + 1 < NT);
        if (more) {
            // prefetch K(t+1) via cp.async, V(t+1) into regs
            const float* kg = kgBase + (size_t)(t + 1) * 64 * ldk;
            cp_async16(ksA[cur ^ 1] + kstOff,      kg);
            cp_async16(ksA[cur ^ 1] + kstOff + 16, kg + 4);
            asm volatile("cp.async.commit_group;\n");
            const float* vg = vgBase + (size_t)(t + 1) * 64 * ldv;
            vA = *(const float4*)vg;
            vB = *(const float4*)(vg + 4);
        }

        // S = Q @ K^T (16x64 per warp)
        float accs[8][4];
#pragma unroll
        for (int ni = 0; ni < 8; ni++)
#pragma unroll
            for (int tt = 0; tt < 4; tt++) accs[ni][tt] = 0.f;
#pragma unroll
        for (int kb = 0; kb < 4; kb++) {
#pragma unroll
            for (int p = 0; p < 4; p++) {
                uint32_t bf[4];
                ldsm_x4(bf, ksA[cur] + ((p * 16 + brow) * 36 + kb * 8 + bcol) * 4);
                mma_tf32(accs[2*p],   qf[kb][0], qf[kb][1], qf[kb][2], qf[kb][3], bf[0], bf[1]);
                mma_tf32(accs[2*p+1], qf[kb][0], qf[kb][1], qf[kb][2], qf[kb][3], bf[2], bf[3]);
            }
        }

        // P = exp(S); row sums; store into warp-private PQ rows
#pragma unroll
        for (int ni = 0; ni < 8; ni++) {
            float p0 = __expf(accs[ni][0]);
            float p1 = __expf(accs[ni][1]);
            float p2 = __expf(accs[ni][2]);
            float p3 = __expf(accs[ni][3]);
            rs0 += p0 + p1;
            rs1 += p2 + p3;
            int c0 = (m0 + lr) * 68 + ni * 8 + 2 * lc;
            int c1 = (m0 + 8 + lr) * 68 + ni * 8 + 2 * lc;
            *(float2*)(PQ + c0) = make_float2(p0, p1);
            *(float2*)(PQ + c1) = make_float2(p2, p3);
        }
        __syncwarp();

        // O += P @ V
#pragma unroll
        for (int kb = 0; kb < 8; kb++) {
            uint32_t af[4];
            ldsm_x4(af, pOffA + kb * 32);
#pragma unroll
            for (int p = 0; p < 2; p++) {
                uint32_t bf[4];
                ldsm_x4(bf, vtA + ((p * 16 + brow) * 68 + kb * 8 + bcol) * 4);
                mma_tf32(acc_o[2*p],   af[0], af[1], af[2], af[3], bf[0], bf[1]);
                mma_tf32(acc_o[2*p+1], af[0], af[1], af[2], af[3], bf[2], bf[3]);
            }
        }
        __syncthreads();   // all warps done reading Vt (+ Ks[cur])

        if (more) {
            asm volatile("cp.async.wait_group 0;\n");
            vtDst[0*68] = __float_as_uint(vA.x); vtDst[1*68] = __float_as_uint(vA.y);
            vtDst[2*68] = __float_as_uint(vA.z); vtDst[3*68] = __float_as_uint(vA.w);
            vtDst[4*68] = __float_as_uint(vB.x); vtDst[5*68] = __float_as_uint(vB.y);
            vtDst[6*68] = __float_as_uint(vB.z); vtDst[7*68] = __float_as_uint(vB.w);
            __syncthreads();   // Vt/Ks ready for next tile
        }
    }

    rs0 += __shfl_xor_sync(0xffffffff, rs0, 1);
    rs0 += __shfl_xor_sync(0xffffffff, rs0, 2);
    rs1 += __shfl_xor_sync(0xffffffff, rs1, 1);
    rs1 += __shfl_xor_sync(0xffffffff, rs1, 2);
    float inv0 = 1.f / rs0;
    float inv1 = 1.f / rs1;

#pragma unroll
    for (int ni = 0; ni < 4; ni++) {
        int col = h * DHH + ni * 8 + 2 * lc;
        size_t row0 = (size_t)(b * QQ + q0 + m0 + lr) * EE + col;
        size_t row1 = (size_t)(b * QQ + q0 + m0 + 8 + lr) * EE + col;
        *(float2*)(Om + row0) = make_float2(acc_o[ni][0] * inv0, acc_o[ni][1] * inv0);
        *(float2*)(Om + row1) = make_float2(acc_o[ni][2] * inv1, acc_o[ni][3] * inv1);
    }
}

// ---------------- residual add + LayerNorm (rows of 256) ----------------
__global__ void addln_kernel(const float* __restrict__ X, const float* __restrict__ Y,
                             const float* __restrict__ gam, const float* __restrict__ bet,
                             float* __restrict__ out) {
    int row = blockIdx.x;
    int t = threadIdx.x;
    size_t base = (size_t)row * EE;
    float x = X[base + t] + Y[base + t];

    __shared__ float red[8];
    __shared__ float mu_s, rstd_s;

    float s = x;
#pragma unroll
    for (int o = 16; o > 0; o >>= 1) s += __shfl_down_sync(0xffffffff, s, o);
    if ((t & 31) == 0) red[t >> 5] = s;
    __syncthreads();
    if (t == 0) {
        float tot = 0.f;
#pragma unroll
        for (int i = 0; i < 8; i++) tot += red[i];
        mu_s = tot * (1.f / EE);
    }
    __syncthreads();
    float mu = mu_s;
    float d = x - mu;
    float s2 = d * d;
#pragma unroll
    for (int o = 16; o > 0; o >>= 1) s2 += __shfl_down_sync(0xffffffff, s2, o);
    if ((t & 31) == 0) red[t >> 5] = s2;
    __syncthreads();
    if (t == 0) {
        float tot = 0.f;
#pragma unroll
        for (int i = 0; i < 8; i++) tot += red[i];
        rstd_s = rsqrtf(tot * (1.f / EE) + 1e-5f);
    }
    __syncthreads();
    out[base + t] = (x - mu) * rstd_s * gam[t] + bet[t];
}

// ---------------- attention-weight softmax over L*P=16 ----------------
__global__ void awsm_kernel(float* __restrict__ aw) {
    int i = blockIdx.x * blockDim.x + threadIdx.x;
    if (i >= BB * QQ * NHH) return;
    float* p = aw + (size_t)i * 16;
    float v[16];
    float m = -1e30f;
#pragma unroll
    for (int j = 0; j < 16; j++) { v[j] = p[j]; m = fmaxf(m, v[j]); }
    float s = 0.f;
#pragma unroll
    for (int j = 0; j < 16; j++) { v[j] = __expf(v[j] - m); s += v[j]; }
    float inv = 1.f / s;
#pragma unroll
    for (int j = 0; j < 16; j++) p[j] = v[j] * inv;
}

// ---------------- deformable bilinear sampling ----------------
__device__ __forceinline__ float fetch_corner(const float* __restrict__ vb,
                                              float yi, float xi, int Hl, int Wl) {
    bool valid = (xi >= 0.f) && (xi <= (float)(Wl - 1)) &&
                 (yi >= 0.f) && (yi <= (float)(Hl - 1));
    int xc = (int)fminf(fmaxf(xi, 0.f), (float)(Wl - 1));
    int yc = (int)fminf(fmaxf(yi, 0.f), (float)(Hl - 1));
    float v = vb[(size_t)(yc * Wl + xc) * EE];
    return valid ? v : 0.f;
}

__global__ void sample_kernel(const float* __restrict__ refp, const float* __restrict__ off,
                              const float* __restrict__ aw, const float* __restrict__ val,
                              float* __restrict__ out) {
    int wg = (blockIdx.x * blockDim.x + threadIdx.x) >> 5;
    int lane = threadIdx.x & 31;
    if (wg >= BB * QQ * NHH) return;
    int h = wg % NHH;
    int bq = wg / NHH;
    int b = bq / QQ;

    const float* rp = refp + (size_t)bq * (LLV * 2);
    const float* op = off + (size_t)bq * 256 + h * 32;
    const float* ap = aw + (size_t)bq * 128 + h * 16;

    const int Hs[4] = {128, 64, 32, 16};
    const int Ws2[4] = {128, 64, 32, 16};
    const int S0[4] = {0, 16384, 20480, 21504};

    float acc = 0.f;
#pragma unroll
    for (int l = 0; l < 4; l++) {
        int Hi = Hs[l], Wi = Ws2[l];
        float Hl = (float)Hi, Wl = (float)Wi;
        const float* vb = val + ((size_t)b * STOT + S0[l]) * EE + h * 32 + lane;
        float rx = rp[l * 2 + 0], ry = rp[l * 2 + 1];
#pragma unroll
        for (int p = 0; p < 4; p++) {
            float ox = op[l * 8 + p * 2 + 0];
            float oy = op[l * 8 + p * 2 + 1];
            float a = ap[l * 4 + p];
            float x = fmaf(rx, Wl, ox) - 0.5f;
            float y = fmaf(ry, Hl, oy) - 0.5f;
            float x0 = floorf(x), y0 = floorf(y);
            float wx = x - x0, wy = y - y0;
            float sum = 0.f;
            sum += fetch_corner(vb, y0,       x0,       Hi, Wi) * (1.f - wy) * (1.f - wx);
            sum += fetch_corner(vb, y0,       x0 + 1.f, Hi, Wi) * (1.f - wy) * wx;
            sum += fetch_corner(vb, y0 + 1.f, x0,       Hi, Wi) * wy * (1.f - wx);
            sum += fetch_corner(vb, y0 + 1.f, x0 + 1.f, Hi, Wi) * wy * wx;
            acc = fmaf(a, sum, acc);
        }
    }
    out[(size_t)bq * EE + h * 32 + lane] = acc;
}

// ---------------- launch ----------------
extern "C" void kernel_launch(void* const* d_in, const int* in_sizes, int n_in,
                              void* d_out, int out_size) {
    const float* tgt   = (const float*)d_in[0];
    const float* qpos  = (const float*)d_in[1];
    const float* refp  = (const float*)d_in[2];
    const float* src   = (const float*)d_in[3];
    const float* ipw   = (const float*)d_in[6];
    const float* ipb   = (const float*)d_in[7];
    const float* outpw = (const float*)d_in[8];
    const float* outpb = (const float*)d_in[9];
    const float* n1g   = (const float*)d_in[10];
    const float* n1b   = (const float*)d_in[11];
    const float* offw  = (const float*)d_in[12];
    const float* offb  = (const float*)d_in[13];
    const float* aww   = (const float*)d_in[14];
    const float* awb   = (const float*)d_in[15];
    const float* vpw   = (const float*)d_in[16];
    const float* vpb   = (const float*)d_in[17];
    const float* opw   = (const float*)d_in[18];
    const float* opb   = (const float*)d_in[19];
    const float* n2g   = (const float*)d_in[20];
    const float* n2b   = (const float*)d_in[21];
    const float* w1    = (const float*)d_in[22];
    const float* b1    = (const float*)d_in[23];
    const float* w2    = (const float*)d_in[24];
    const float* b2    = (const float*)d_in[25];
    const float* n3g   = (const float*)d_in[26];
    const float* n3b   = (const float*)d_in[27];
    float* out = (float*)d_out;

    float *qk, *qk2, *v, *ctx, *tmp, *tgt1, *query, *value, *off, *aw, *samp, *tgt2, *ffn1;
    cudaGetSymbolAddress((void**)&qk,    g_qk);
    cudaGetSymbolAddress((void**)&qk2,   g_qk2);
    cudaGetSymbolAddress((void**)&v,     g_v);
    cudaGetSymbolAddress((void**)&ctx,   g_ctx);
    cudaGetSymbolAddress((void**)&tmp,   g_tmp);
    cudaGetSymbolAddress((void**)&tgt1,  g_tgt1);
    cudaGetSymbolAddress((void**)&query, g_query);
    cudaGetSymbolAddress((void**)&value, g_value);
    cudaGetSymbolAddress((void**)&off,   g_off);
    cudaGetSymbolAddress((void**)&aw,    g_aw);
    cudaGetSymbolAddress((void**)&samp,  g_samp);
    cudaGetSymbolAddress((void**)&tgt2,  g_tgt2);
    cudaGetSymbolAddress((void**)&ffn1,  g_ffn1);

    cudaFuncSetAttribute(gemm_tc<0>, cudaFuncAttributeMaxDynamicSharedMemorySize, GEMM_SMEM);
    cudaFuncSetAttribute(gemm_tc<1>, cudaFuncAttributeMaxDynamicSharedMemorySize, GEMM_SMEM);
    cudaFuncSetAttribute(attn_tc,    cudaFuncAttributeMaxDynamicSharedMemorySize, ATT_SMEM_BYTES);

    const int M = BB * QQ;
    const int n_el = M * EE;

    add_kernel<<<(n_el / 4 + 255) / 256, 256>>>((const float4*)tgt, (const float4*)qpos,
                                                (float4*)qk, n_el / 4);

    gemm_tc<0><<<dim3(4, M / 128), 256, GEMM_SMEM>>>(qk,  ipw,             ipb,       qk2, M, 512, 256);
    gemm_tc<0><<<dim3(2, M / 128), 256, GEMM_SMEM>>>(tgt, ipw + 512 * 256, ipb + 512, v,   M, 256, 256);

    attn_tc<<<dim3(QQ / 128, BB * NHH), 256, ATT_SMEM_BYTES>>>(qk2, 512, qk2 + 256, 512, v, 256, ctx);

    gemm_tc<0><<<dim3(2, M / 128), 256, GEMM_SMEM>>>(ctx, outpw, outpb, tmp, M, 256, 256);
    addln_kernel<<<M, 256>>>(tgt, tmp, n1g, n1b, tgt1);

    add_kernel<<<(n_el / 4 + 255) / 256, 256>>>((const float4*)tgt1, (const float4*)qpos,
                                                (float4*)query, n_el / 4);

    gemm_tc<0><<<dim3(2, (BB * STOT) / 128), 256, GEMM_SMEM>>>(src, vpw, vpb, value, BB * STOT, 256, 256);

    gemm_tc<0><<<dim3(2, M / 128), 256, GEMM_SMEM>>>(query, offw, offb, off, M, 256, 256);
    gemm_tc<0><<<dim3(1, M / 128), 256, GEMM_SMEM>>>(query, aww, awb, aw, M, 128, 256);
    awsm_kernel<<<(BB * QQ * NHH + 255) / 256, 256>>>(aw);

    sample_kernel<<<(BB * QQ * NHH) / 8, 256>>>(refp, off, aw, value, samp);

    gemm_tc<0><<<dim3(2, M / 128), 256, GEMM_SMEM>>>(samp, opw, opb, tmp, M, 256, 256);
    addln_kernel<<<M, 256>>>(tgt1, tmp, n2g, n2b, tgt2);

    gemm_tc<1><<<dim3(8, M / 128), 256, GEMM_SMEM>>>(tgt2, w1, b1, ffn1, M, 1024, 256);
    gemm_tc<0><<<dim3(2, M / 128), 256, GEMM_SMEM>>>(ffn1, w2, b2, tmp, M, 256, 1024);
    addln_kernel<<<M, 256>>>(tgt2, tmp, n3g, n3b, out);
}

// round 7
// speedup vs baseline: 2.3175x; 1.3299x over previous
#include <cuda_runtime.h>
#include <cuda_fp16.h>
#include <math.h>
#include <stdint.h>

#define BB   8
#define QQ   1024
#define EE   256
#define NHH  8
#define DHH  32
#define STOT 21760
#define MM   (BB*QQ)

// ---------------- scratch (device globals: allocation-free) ----------------
__device__ float g_value[(size_t)BB*STOT*EE];
__device__ float g_tmp  [MM*EE];
__device__ float g_tgt1 [MM*EE];
__device__ float g_tgt2 [MM*EE];
__device__ float g_off  [MM*EE];
__device__ float g_aw   [MM*128];

__device__ __half h_tgt  [MM*EE];
__device__ __half h_src  [(size_t)BB*STOT*EE];
__device__ __half h_ipw  [768*256];
__device__ __half h_outpw[256*256];
__device__ __half h_offw [256*256];
__device__ __half h_aww  [128*256];
__device__ __half h_vpw  [256*256];
__device__ __half h_opw  [256*256];
__device__ __half h_w1   [1024*256];
__device__ __half h_w2   [256*1024];
__device__ __half h_qk   [MM*EE];
__device__ __half h_qk2  [MM*512];
__device__ __half h_v    [MM*EE];
__device__ __half h_ctx  [MM*EE];
__device__ __half h_query[MM*EE];
__device__ __half h_samp [MM*EE];
__device__ __half h_tgt2 [MM*EE];
__device__ __half h_ffn1 [MM*1024];

// ---------------- helpers ----------------
__device__ __forceinline__ void mma_f16(float* c,
                                        uint32_t a0, uint32_t a1, uint32_t a2, uint32_t a3,
                                        uint32_t b0, uint32_t b1) {
    asm volatile("mma.sync.aligned.m16n8k16.row.col.f32.f16.f16.f32 "
                 "{%0,%1,%2,%3}, {%4,%5,%6,%7}, {%8,%9}, {%0,%1,%2,%3};\n"
                 : "+f"(c[0]), "+f"(c[1]), "+f"(c[2]), "+f"(c[3])
                 : "r"(a0), "r"(a1), "r"(a2), "r"(a3), "r"(b0), "r"(b1));
}

__device__ __forceinline__ void ldsm_x4(uint32_t* r, uint32_t addr) {
    asm volatile("ldmatrix.sync.aligned.m8n8.x4.shared.b16 {%0,%1,%2,%3}, [%4];\n"
                 : "=r"(r[0]), "=r"(r[1]), "=r"(r[2]), "=r"(r[3]) : "r"(addr));
}

__device__ __forceinline__ void cp_async16(uint32_t smem_addr, const void* gmem) {
    asm volatile("cp.async.ca.shared.global [%0], [%1], 16;\n" :: "r"(smem_addr), "l"(gmem));
}

__device__ __forceinline__ uint32_t packh2(float a, float b) {
    __half2 h = __floats2half2_rn(a, b);
    return *(uint32_t*)&h;
}

// ---------------- bulk fp32 -> fp16 convert (10 segments) ----------------
struct CvtArgs {
    const float* s[10];
    __half* d[10];
    int n8[10];
};
__global__ void cvt_kernel(CvtArgs a, int total8) {
    int i = blockIdx.x * blockDim.x + threadIdx.x;
    if (i >= total8) return;
    int seg = 0;
#pragma unroll
    for (int k = 0; k < 10; k++) {
        if (i >= a.n8[seg]) { i -= a.n8[seg]; seg++; } else break;
    }
    const float4* sp = (const float4*)a.s[seg] + (size_t)i * 2;
    float4 x = sp[0], y = sp[1];
    uint4 o;
    o.x = packh2(x.x, x.y); o.y = packh2(x.z, x.w);
    o.z = packh2(y.x, y.y); o.w = packh2(y.z, y.w);
    ((uint4*)a.d[seg])[i] = o;
}

// ---------------- add (f32 + f32 -> f16) ----------------
__global__ void add_h(const float4* __restrict__ a, const float4* __restrict__ b,
                      __half* __restrict__ c, int n4) {
    int i = blockIdx.x * blockDim.x + threadIdx.x;
    if (i >= n4) return;
    float4 x = a[i], y = b[i];
    uint2 o;
    o.x = packh2(x.x + y.x, x.y + y.y);
    o.y = packh2(x.z + y.z, x.w + y.w);
    ((uint2*)c)[i] = o;
}

// ---------------- fp16 tensor-core GEMM ----------------
// C[M,N] = A[M,K] @ W[N,K]^T + bias. 128x128 tile, 8 warps (4m x 2n), k-chunk 64.
#define HSMS 72                    // halves per smem row (64 + 8 pad)
#define HSTG (128 * HSMS)          // halves per stage per matrix
template<int RELU, int WF32, int WF16>
__global__ __launch_bounds__(256, 2)
void gemm_h(const __half* __restrict__ A, const __half* __restrict__ W,
            const float* __restrict__ bias, float* __restrict__ C,
            __half* __restrict__ Ch, int M, int N, int K) {
    extern __shared__ __half smh[];
    const uint32_t base = (uint32_t)__cvta_generic_to_shared(smh);
    uint32_t AsmA[2] = { base,               base + HSTG * 2 };
    uint32_t WsmA[2] = { base + 2*HSTG*2,    base + 3*HSTG*2 };

    const int bm = blockIdx.y * 128;
    const int bn = blockIdx.x * 128;
    const int tid  = threadIdx.x;
    const int warp = tid >> 5;
    const int lane = tid & 31;
    const int wm = warp >> 1;
    const int wn = warp & 1;
    const int lr = lane >> 2;
    const int lc = lane & 3;
    const int l16 = lane & 15;
    const int l4  = lane >> 4;

    uint32_t aOff[2], bOff[4];
#pragma unroll
    for (int mi = 0; mi < 2; mi++)
        aOff[mi] = (wm * 32 + mi * 16 + l16) * (HSMS * 2) + l4 * 16;
#pragma unroll
    for (int p = 0; p < 4; p++)
        bOff[p] = (wn * 64 + p * 16 + l16) * (HSMS * 2) + l4 * 16;

    float acc[2][8][4];
#pragma unroll
    for (int mi = 0; mi < 2; mi++)
#pragma unroll
        for (int ni = 0; ni < 8; ni++)
#pragma unroll
            for (int t = 0; t < 4; t++) acc[mi][ni][t] = 0.f;

    const int lrow = tid >> 1;
    const int lseg = tid & 1;
    const __half* Ag = A + (size_t)(bm + lrow) * K + lseg * 32;
    const __half* Wg = W + (size_t)(bn + lrow) * K + lseg * 32;
    uint32_t aSt[2], wSt[2];
#pragma unroll
    for (int s = 0; s < 2; s++) {
        aSt[s] = AsmA[s] + lrow * (HSMS * 2) + lseg * 64;
        wSt[s] = WsmA[s] + lrow * (HSMS * 2) + lseg * 64;
    }

    const int nch = K >> 6;

#pragma unroll
    for (int j = 0; j < 4; j++) {
        cp_async16(aSt[0] + j * 16, Ag + j * 8);
        cp_async16(wSt[0] + j * 16, Wg + j * 8);
    }
    asm volatile("cp.async.commit_group;\n");

    for (int c = 0; c < nch; c++) {
        const int cur = c & 1;
        if (c + 1 < nch) {
            const __half* Agn = Ag + (size_t)(c + 1) * 64;
            const __half* Wgn = Wg + (size_t)(c + 1) * 64;
            const int nxt = cur ^ 1;
#pragma unroll
            for (int j = 0; j < 4; j++) {
                cp_async16(aSt[nxt] + j * 16, Agn + j * 8);
                cp_async16(wSt[nxt] + j * 16, Wgn + j * 8);
            }
            asm volatile("cp.async.commit_group;\n");
            asm volatile("cp.async.wait_group 1;\n");
        } else {
            asm volatile("cp.async.wait_group 0;\n");
        }
        __syncthreads();

        const uint32_t aS = AsmA[cur];
        const uint32_t wS = WsmA[cur];
#pragma unroll
        for (int kk = 0; kk < 4; kk++) {
            uint32_t a0[4], a1[4];
            ldsm_x4(a0, aS + aOff[0] + kk * 32);
            ldsm_x4(a1, aS + aOff[1] + kk * 32);
#pragma unroll
            for (int p = 0; p < 4; p++) {
                uint32_t bf[4];
                ldsm_x4(bf, wS + bOff[p] + kk * 32);
                mma_f16(acc[0][2*p],   a0[0], a0[1], a0[2], a0[3], bf[0], bf[2]);
                mma_f16(acc[1][2*p],   a1[0], a1[1], a1[2], a1[3], bf[0], bf[2]);
                mma_f16(acc[0][2*p+1], a0[0], a0[1], a0[2], a0[3], bf[1], bf[3]);
                mma_f16(acc[1][2*p+1], a1[0], a1[1], a1[2], a1[3], bf[1], bf[3]);
            }
        }
        __syncthreads();
    }

#pragma unroll
    for (int ni = 0; ni < 8; ni++) {
        int col = bn + wn * 64 + ni * 8 + lc * 2;
        float bj0 = bias[col], bj1 = bias[col + 1];
#pragma unroll
        for (int mi = 0; mi < 2; mi++) {
            int row = bm + wm * 32 + mi * 16 + lr;
            float v0 = acc[mi][ni][0] + bj0;
            float v1 = acc[mi][ni][1] + bj1;
            float v2 = acc[mi][ni][2] + bj0;
            float v3 = acc[mi][ni][3] + bj1;
            if (RELU) {
                v0 = fmaxf(v0, 0.f); v1 = fmaxf(v1, 0.f);
                v2 = fmaxf(v2, 0.f); v3 = fmaxf(v3, 0.f);
            }
            if (WF32) {
                *(float2*)(C + (size_t)row * N + col)       = make_float2(v0, v1);
                *(float2*)(C + (size_t)(row + 8) * N + col) = make_float2(v2, v3);
            }
            if (WF16) {
                *(uint32_t*)(Ch + (size_t)row * N + col)       = packh2(v0, v1);
                *(uint32_t*)(Ch + (size_t)(row + 8) * N + col) = packh2(v2, v3);
            }
        }
    }
}
#define GEMMH_SMEM (4 * HSTG * 2)

// ---------------- fp16 tensor-core self-attention ----------------
// smem (halves): Q[128][40] | Ks[2][64][40] | Vt[32][72] | P[128][72]
#define AQ_OFF  0
#define AK0_OFF 5120
#define AK1_OFF 7680
#define AV_OFF  10240
#define AP_OFF  12544
#define ATT_SMEM_BYTES ((12544 + 9216) * 2)

__global__ __launch_bounds__(256, 2)
void attn_h(const __half* __restrict__ Qm, int ldq,
            const __half* __restrict__ Km, int ldk,
            const __half* __restrict__ Vm, int ldv,
            __half* __restrict__ Om) {
    extern __shared__ __half sh[];
    const uint32_t shA = (uint32_t)__cvta_generic_to_shared(sh);
    const uint32_t qA  = shA + AQ_OFF * 2;
    uint32_t ksA[2] = { shA + AK0_OFF * 2, shA + AK1_OFF * 2 };
    const uint32_t vtA = shA + AV_OFF * 2;
    const uint32_t pA  = shA + AP_OFF * 2;
    __half* Vts = sh + AV_OFF;
    __half* Ps  = sh + AP_OFF;

    const int bh = blockIdx.y;
    const int b = bh / NHH, h = bh % NHH;
    const int q0 = blockIdx.x * 128;
    const int tid = threadIdx.x;
    const int warp = tid >> 5;
    const int lane = tid & 31;
    const int lr = lane >> 2;
    const int lc = lane & 3;
    const int l16 = lane & 15;
    const int l4  = lane >> 4;
    const int m0 = warp * 16;
    const float scale = 0.17677669529663687f;

    // Q stage: row tid>>1, 32B seg tid&1
    {
        const int lrow = tid >> 1, lseg = tid & 1;
        const __half* qp = Qm + (size_t)(b * QQ + q0 + lrow) * ldq + h * DHH + lseg * 16;
        uint32_t dst = qA + lrow * 80 + lseg * 32;
        cp_async16(dst, qp);
        cp_async16(dst + 16, qp + 8);
    }
    // K tile 0: row tid>>2, 16B seg tid&3
    const int krow = tid >> 2;
    const int kseg = tid & 3;
    const __half* kgBase = Km + (size_t)(b * QQ + krow) * ldk + h * DHH + kseg * 8;
    const uint32_t kstOff = krow * 80 + kseg * 16;
    cp_async16(ksA[0] + kstOff, kgBase);
    asm volatile("cp.async.commit_group;\n");

    // V tile 0 prefetch (permuted conflict-free scatter)
    const int vc = tid & 3;
    const int vr = tid >> 2;
    const int vkc = vc * 8;
    const int vkr = (vr + 8 * vc) & 63;
    const __half* vgBase = Vm + (size_t)(b * QQ + vkr) * ldv + h * DHH + vkc;
    __half* vtDst = Vts + vkc * 72 + vkr;
    uint4 vReg = *(const uint4*)vgBase;

    asm volatile("cp.async.wait_group 0;\n");
    __syncthreads();

    uint32_t qf[2][4];
#pragma unroll
    for (int kb = 0; kb < 2; kb++)
        ldsm_x4(qf[kb], qA + (m0 + l16) * 80 + l4 * 16 + kb * 32);

    {
        const __half* vh = (const __half*)&vReg;
#pragma unroll
        for (int j = 0; j < 8; j++) vtDst[j * 72] = vh[j];
    }
    __syncthreads();

    float acc_o[4][4];
#pragma unroll
    for (int ni = 0; ni < 4; ni++)
#pragma unroll
        for (int t = 0; t < 4; t++) acc_o[ni][t] = 0.f;
    float rs0 = 0.f, rs1 = 0.f;

    const int NT = QQ / 64;
    for (int t = 0; t < NT; t++) {
        const int cur = t & 1;
        const bool more = (t + 1 < NT);
        if (more) {
            cp_async16(ksA[cur ^ 1] + kstOff, kgBase + (size_t)(t + 1) * 64 * ldk);
            asm volatile("cp.async.commit_group;\n");
            vReg = *(const uint4*)(vgBase + (size_t)(t + 1) * 64 * ldv);
        }

        // S = Q @ K^T (16x64 per warp)
        float accs[8][4];
#pragma unroll
        for (int ni = 0; ni < 8; ni++)
#pragma unroll
            for (int tt = 0; tt < 4; tt++) accs[ni][tt] = 0.f;
#pragma unroll
        for (int kb = 0; kb < 2; kb++) {
#pragma unroll
            for (int p = 0; p < 4; p++) {
                uint32_t bf[4];
                ldsm_x4(bf, ksA[cur] + (p * 16 + l16) * 80 + l4 * 16 + kb * 32);
                mma_f16(accs[2*p],   qf[kb][0], qf[kb][1], qf[kb][2], qf[kb][3], bf[0], bf[2]);
                mma_f16(accs[2*p+1], qf[kb][0], qf[kb][1], qf[kb][2], qf[kb][3], bf[1], bf[3]);
            }
        }

        // P = exp(S*scale); row sums; store half2 into warp-private P rows
#pragma unroll
        for (int ni = 0; ni < 8; ni++) {
            float p0 = __expf(accs[ni][0] * scale);
            float p1 = __expf(accs[ni][1] * scale);
            float p2 = __expf(accs[ni][2] * scale);
            float p3 = __expf(accs[ni][3] * scale);
            rs0 += p0 + p1;
            rs1 += p2 + p3;
            *(uint32_t*)(Ps + (m0 + lr) * 72 + ni * 8 + 2 * lc)     = packh2(p0, p1);
            *(uint32_t*)(Ps + (m0 + 8 + lr) * 72 + ni * 8 + 2 * lc) = packh2(p2, p3);
        }
        __syncwarp();

        // O += P @ V (16x32 per warp, k=64)
#pragma unroll
        for (int kb = 0; kb < 4; kb++) {
            uint32_t af[4];
            ldsm_x4(af, pA + (m0 + l16) * 144 + l4 * 16 + kb * 32);
#pragma unroll
            for (int p = 0; p < 2; p++) {
                uint32_t bf[4];
                ldsm_x4(bf, vtA + (p * 16 + l16) * 144 + l4 * 16 + kb * 32);
                mma_f16(acc_o[2*p],   af[0], af[1], af[2], af[3], bf[0], bf[2]);
                mma_f16(acc_o[2*p+1], af[0], af[1], af[2], af[3], bf[1], bf[3]);
            }
        }
        __syncthreads();

        if (more) {
            asm volatile("cp.async.wait_group 0;\n");
            const __half* vh = (const __half*)&vReg;
#pragma unroll
            for (int j = 0; j < 8; j++) vtDst[j * 72] = vh[j];
            __syncthreads();
        }
    }

    rs0 += __shfl_xor_sync(0xffffffff, rs0, 1);
    rs0 += __shfl_xor_sync(0xffffffff, rs0, 2);
    rs1 += __shfl_xor_sync(0xffffffff, rs1, 1);
    rs1 += __shfl_xor_sync(0xffffffff, rs1, 2);
    float inv0 = 1.f / rs0;
    float inv1 = 1.f / rs1;

#pragma unroll
    for (int ni = 0; ni < 4; ni++) {
        int col = h * DHH + ni * 8 + 2 * lc;
        size_t row0 = (size_t)(b * QQ + q0 + m0 + lr) * EE + col;
        size_t row1 = (size_t)(b * QQ + q0 + m0 + 8 + lr) * EE + col;
        *(uint32_t*)(Om + row0) = packh2(acc_o[ni][0] * inv0, acc_o[ni][1] * inv0);
        *(uint32_t*)(Om + row1) = packh2(acc_o[ni][2] * inv1, acc_o[ni][3] * inv1);
    }
}

// ---------------- residual add + LayerNorm (rows of 256) ----------------
__global__ void addln_kernel(const float* __restrict__ X, const float* __restrict__ Y,
                             const float* __restrict__ gam, const float* __restrict__ bet,
                             float* __restrict__ out, __half* __restrict__ hout) {
    int row = blockIdx.x;
    int t = threadIdx.x;
    size_t base = (size_t)row * EE;
    float x = X[base + t] + Y[base + t];

    __shared__ float red[8];
    __shared__ float mu_s, rstd_s;

    float s = x;
#pragma unroll
    for (int o = 16; o > 0; o >>= 1) s += __shfl_down_sync(0xffffffff, s, o);
    if ((t & 31) == 0) red[t >> 5] = s;
    __syncthreads();
    if (t == 0) {
        float tot = 0.f;
#pragma unroll
        for (int i = 0; i < 8; i++) tot += red[i];
        mu_s = tot * (1.f / EE);
    }
    __syncthreads();
    float mu = mu_s;
    float d = x - mu;
    float s2 = d * d;
#pragma unroll
    for (int o = 16; o > 0; o >>= 1) s2 += __shfl_down_sync(0xffffffff, s2, o);
    if ((t & 31) == 0) red[t >> 5] = s2;
    __syncthreads();
    if (t == 0) {
        float tot = 0.f;
#pragma unroll
        for (int i = 0; i < 8; i++) tot += red[i];
        rstd_s = rsqrtf(tot * (1.f / EE) + 1e-5f);
    }
    __syncthreads();
    float val = (x - mu) * rstd_s * gam[t] + bet[t];
    out[base + t] = val;
    if (hout) hout[base + t] = __float2half_rn(val);
}

// ---------------- attention-weight softmax over 16 ----------------
__global__ void awsm_kernel(float* __restrict__ aw) {
    int i = blockIdx.x * blockDim.x + threadIdx.x;
    if (i >= BB * QQ * NHH) return;
    float* p = aw + (size_t)i * 16;
    float v[16];
    float m = -1e30f;
#pragma unroll
    for (int j = 0; j < 16; j++) { v[j] = p[j]; m = fmaxf(m, v[j]); }
    float s = 0.f;
#pragma unroll
    for (int j = 0; j < 16; j++) { v[j] = __expf(v[j] - m); s += v[j]; }
    float inv = 1.f / s;
#pragma unroll
    for (int j = 0; j < 16; j++) p[j] = v[j] * inv;
}

// ---------------- deformable bilinear sampling ----------------
__device__ __forceinline__ float fetch_corner(const float* __restrict__ vb,
                                              float yi, float xi, int Hl, int Wl) {
    bool valid = (xi >= 0.f) && (xi <= (float)(Wl - 1)) &&
                 (yi >= 0.f) && (yi <= (float)(Hl - 1));
    int xc = (int)fminf(fmaxf(xi, 0.f), (float)(Wl - 1));
    int yc = (int)fminf(fmaxf(yi, 0.f), (float)(Hl - 1));
    float v = vb[(size_t)(yc * Wl + xc) * EE];
    return valid ? v : 0.f;
}

__global__ void sample_kernel(const float* __restrict__ refp, const float* __restrict__ off,
                              const float* __restrict__ aw, const float* __restrict__ val,
                              __half* __restrict__ out) {
    int wg = (blockIdx.x * blockDim.x + threadIdx.x) >> 5;
    int lane = threadIdx.x & 31;
    if (wg >= BB * QQ * NHH) return;
    int h = wg % NHH;
    int bq = wg / NHH;
    int b = bq / QQ;

    const float* rp = refp + (size_t)bq * 8;
    const float* op = off + (size_t)bq * 256 + h * 32;
    const float* ap = aw + (size_t)bq * 128 + h * 16;

    const int Hs[4] = {128, 64, 32, 16};
    const int S0[4] = {0, 16384, 20480, 21504};

    float acc = 0.f;
#pragma unroll
    for (int l = 0; l < 4; l++) {
        int Hi = Hs[l], Wi = Hs[l];
        float Hl = (float)Hi, Wl = (float)Wi;
        const float* vb = val + ((size_t)b * STOT + S0[l]) * EE + h * 32 + lane;
        float rx = rp[l * 2 + 0], ry = rp[l * 2 + 1];
#pragma unroll
        for (int p = 0; p < 4; p++) {
            float ox = op[l * 8 + p * 2 + 0];
            float oy = op[l * 8 + p * 2 + 1];
            float a = ap[l * 4 + p];
            float x = fmaf(rx, Wl, ox) - 0.5f;
            float y = fmaf(ry, Hl, oy) - 0.5f;
            float x0 = floorf(x), y0 = floorf(y);
            float wx = x - x0, wy = y - y0;
            float sum = 0.f;
            sum += fetch_corner(vb, y0,       x0,       Hi, Wi) * (1.f - wy) * (1.f - wx);
            sum += fetch_corner(vb, y0,       x0 + 1.f, Hi, Wi) * (1.f - wy) * wx;
            sum += fetch_corner(vb, y0 + 1.f, x0,       Hi, Wi) * wy * (1.f - wx);
            sum += fetch_corner(vb, y0 + 1.f, x0 + 1.f, Hi, Wi) * wy * wx;
            acc = fmaf(a, sum, acc);
        }
    }
    out[(size_t)bq * EE + h * 32 + lane] = __float2half_rn(acc);
}

// ---------------- launch ----------------
extern "C" void kernel_launch(void* const* d_in, const int* in_sizes, int n_in,
                              void* d_out, int out_size) {
    const float* tgt   = (const float*)d_in[0];
    const float* qpos  = (const float*)d_in[1];
    const float* refp  = (const float*)d_in[2];
    const float* src   = (const float*)d_in[3];
    const float* ipw   = (const float*)d_in[6];
    const float* ipb   = (const float*)d_in[7];
    const float* outpw = (const float*)d_in[8];
    const float* outpb = (const float*)d_in[9];
    const float* n1g   = (const float*)d_in[10];
    const float* n1b   = (const float*)d_in[11];
    const float* offw  = (const float*)d_in[12];
    const float* offb  = (const float*)d_in[13];
    const float* aww   = (const float*)d_in[14];
    const float* awb   = (const float*)d_in[15];
    const float* vpw   = (const float*)d_in[16];
    const float* vpb   = (const float*)d_in[17];
    const float* opw   = (const float*)d_in[18];
    const float* opb   = (const float*)d_in[19];
    const float* n2g   = (const float*)d_in[20];
    const float* n2b   = (const float*)d_in[21];
    const float* w1    = (const float*)d_in[22];
    const float* b1    = (const float*)d_in[23];
    const float* w2    = (const float*)d_in[24];
    const float* b2    = (const float*)d_in[25];
    const float* n3g   = (const float*)d_in[26];
    const float* n3b   = (const float*)d_in[27];
    float* out = (float*)d_out;

    float *value, *tmp, *tgt1, *tgt2, *off, *aw;
    cudaGetSymbolAddress((void**)&value, g_value);
    cudaGetSymbolAddress((void**)&tmp,   g_tmp);
    cudaGetSymbolAddress((void**)&tgt1,  g_tgt1);
    cudaGetSymbolAddress((void**)&tgt2,  g_tgt2);
    cudaGetSymbolAddress((void**)&off,   g_off);
    cudaGetSymbolAddress((void**)&aw,    g_aw);

    __half *htgt, *hsrc, *hipw, *houtpw, *hoffw, *haww, *hvpw, *hopw, *hw1, *hw2;
    __half *hqk, *hqk2, *hv, *hctx, *hquery, *hsamp, *htgt2, *hffn1;
    cudaGetSymbolAddress((void**)&htgt,   h_tgt);
    cudaGetSymbolAddress((void**)&hsrc,   h_src);
    cudaGetSymbolAddress((void**)&hipw,   h_ipw);
    cudaGetSymbolAddress((void**)&houtpw, h_outpw);
    cudaGetSymbolAddress((void**)&hoffw,  h_offw);
    cudaGetSymbolAddress((void**)&haww,   h_aww);
    cudaGetSymbolAddress((void**)&hvpw,   h_vpw);
    cudaGetSymbolAddress((void**)&hopw,   h_opw);
    cudaGetSymbolAddress((void**)&hw1,    h_w1);
    cudaGetSymbolAddress((void**)&hw2,    h_w2);
    cudaGetSymbolAddress((void**)&hqk,    h_qk);
    cudaGetSymbolAddress((void**)&hqk2,   h_qk2);
    cudaGetSymbolAddress((void**)&hv,     h_v);
    cudaGetSymbolAddress((void**)&hctx,   h_ctx);
    cudaGetSymbolAddress((void**)&hquery, h_query);
    cudaGetSymbolAddress((void**)&hsamp,  h_samp);
    cudaGetSymbolAddress((void**)&htgt2,  h_tgt2);
    cudaGetSymbolAddress((void**)&hffn1,  h_ffn1);

    cudaFuncSetAttribute(gemm_h<0,0,1>, cudaFuncAttributeMaxDynamicSharedMemorySize, GEMMH_SMEM);
    cudaFuncSetAttribute(gemm_h<0,1,0>, cudaFuncAttributeMaxDynamicSharedMemorySize, GEMMH_SMEM);
    cudaFuncSetAttribute(gemm_h<1,0,1>, cudaFuncAttributeMaxDynamicSharedMemorySize, GEMMH_SMEM);
    cudaFuncSetAttribute(attn_h, cudaFuncAttributeMaxDynamicSharedMemorySize, ATT_SMEM_BYTES);

    // 0) bulk convert inputs/weights to fp16
    CvtArgs ca;
    const float* ss[10] = { tgt, src, ipw, outpw, offw, aww, vpw, opw, w1, w2 };
    __half* dd[10] = { htgt, hsrc, hipw, houtpw, hoffw, haww, hvpw, hopw, hw1, hw2 };
    int nn[10] = { MM*EE/8, (int)((size_t)BB*STOT*EE/8), 768*256/8, 65536/8, 65536/8,
                   32768/8, 65536/8, 65536/8, 262144/8, 262144/8 };
    int total8 = 0;
    for (int i = 0; i < 10; i++) { ca.s[i] = ss[i]; ca.d[i] = dd[i]; ca.n8[i] = nn[i]; total8 += nn[i]; }
    cvt_kernel<<<(total8 + 255) / 256, 256>>>(ca, total8);

    const int M = MM;
    const int n4 = M * EE / 4;

    // 1) qk = tgt + query_pos (fp16 out)
    add_h<<<(n4 + 255) / 256, 256>>>((const float4*)tgt, (const float4*)qpos, hqk, n4);

    // 2) q|k merged projection + v projection
    gemm_h<0,0,1><<<dim3(4, M/128), 256, GEMMH_SMEM>>>(hqk, hipw,           ipb,     nullptr, hqk2, M, 512, 256);
    gemm_h<0,0,1><<<dim3(2, M/128), 256, GEMMH_SMEM>>>(htgt, hipw + 512*256, ipb+512, nullptr, hv,   M, 256, 256);

    // 3) self-attention
    attn_h<<<dim3(QQ/128, BB*NHH), 256, ATT_SMEM_BYTES>>>(hqk2, 512, hqk2 + 256, 512, hv, 256, hctx);

    // 4) out projection + LN1
    gemm_h<0,1,0><<<dim3(2, M/128), 256, GEMMH_SMEM>>>(hctx, houtpw, outpb, tmp, nullptr, M, 256, 256);
    addln_kernel<<<M, 256>>>(tgt, tmp, n1g, n1b, tgt1, nullptr);

    // 5) query = tgt1 + query_pos (fp16)
    add_h<<<(n4 + 255) / 256, 256>>>((const float4*)tgt1, (const float4*)qpos, hquery, n4);

    // 6) value projection (174080 x 256 x 256) -> fp32 (sampling precision)
    gemm_h<0,1,0><<<dim3(2, (BB*STOT)/128), 256, GEMMH_SMEM>>>(hsrc, hvpw, vpb, value, nullptr, BB*STOT, 256, 256);

    // 7) offsets + attention weights
    gemm_h<0,1,0><<<dim3(2, M/128), 256, GEMMH_SMEM>>>(hquery, hoffw, offb, off, nullptr, M, 256, 256);
    gemm_h<0,1,0><<<dim3(1, M/128), 256, GEMMH_SMEM>>>(hquery, haww, awb, aw, nullptr, M, 128, 256);
    awsm_kernel<<<(BB*QQ*NHH + 255) / 256, 256>>>(aw);

    // 8) deformable sampling (fp16 out)
    sample_kernel<<<(BB*QQ*NHH) / 8, 256>>>(refp, off, aw, value, hsamp);

    // 9) output projection + LN2
    gemm_h<0,1,0><<<dim3(2, M/128), 256, GEMMH_SMEM>>>(hsamp, hopw, opb, tmp, nullptr, M, 256, 256);
    addln_kernel<<<M, 256>>>(tgt1, tmp, n2g, n2b, tgt2, htgt2);

    // 10) FFN + LN3
    gemm_h<1,0,1><<<dim3(8, M/128), 256, GEMMH_SMEM>>>(htgt2, hw1, b1, nullptr, hffn1, M, 1024, 256);
    gemm_h<0,1,0><<<dim3(2, M/128), 256, GEMMH_SMEM>>>(hffn1, hw2, b2, tmp, nullptr, M, 256, 1024);
    addln_kernel<<<M, 256>>>(tgt2, tmp, n3g, n3b, out, nullptr);
}